// round 14
// baseline (speedup 1.0000x reference)
#include <cuda_runtime.h>
#include <cuda_fp16.h>
#include <math.h>
#include <stdint.h>

#define MB 16384   // rows (2N)
#define DD 2048
#define HH 2048
#define FF 128
#define KK 2048    // K of both big GEMMs

constexpr float INV_T = 1.0f / 0.07f;
constexpr float C_EX2 = 20.6099773964f;   // INV_T * log2(e)

// ---------------- scratch --------------------------------------------------
__device__ __half g_fhi [(size_t)MB * DD];
__device__ __half g_w1hi[(size_t)HH * DD];
__device__ __half g_w2hi[(size_t)FF * HH];
__device__ __half g_hhi [(size_t)MB * HH];
__device__ __half g_zhi [(size_t)MB * FF];
__device__ float g_z  [(size_t)MB * FF];
__device__ float g_ps [(size_t)128 * MB];   // 8MB partial exp-sums [colblk][row]
__device__ float g_lse[MB];
__device__ float g_pos[MB];

// ---------------- helpers ---------------------------------------------------
__device__ __forceinline__ uint32_t smem_u32(const void* p) {
    uint32_t a;
    asm("{ .reg .u64 t; cvta.to.shared.u64 t, %1; cvt.u32.u64 %0, t; }"
        : "=r"(a) : "l"(p));
    return a;
}
__device__ __forceinline__ void cp16(uint32_t s, const void* g) {
    asm volatile("cp.async.cg.shared.global [%0], [%1], 16;" :: "r"(s), "l"(g));
}
#define CP_COMMIT() asm volatile("cp.async.commit_group;")
#define CP_WAIT(n)  asm volatile("cp.async.wait_group %0;" :: "n"(n))

__device__ __forceinline__ void ldsm4(uint32_t* r, uint32_t a) {
    asm volatile("ldmatrix.sync.aligned.m8n8.x4.shared.b16 {%0,%1,%2,%3}, [%4];"
                 : "=r"(r[0]), "=r"(r[1]), "=r"(r[2]), "=r"(r[3]) : "r"(a));
}
__device__ __forceinline__ void mma_f16(float* c, const uint32_t* a,
                                        uint32_t b0, uint32_t b1) {
    asm volatile(
        "mma.sync.aligned.m16n8k16.row.col.f32.f16.f16.f32 "
        "{%0,%1,%2,%3}, {%4,%5,%6,%7}, {%8,%9}, {%0,%1,%2,%3};"
        : "+f"(c[0]), "+f"(c[1]), "+f"(c[2]), "+f"(c[3])
        : "r"(a[0]), "r"(a[1]), "r"(a[2]), "r"(a[3]), "r"(b0), "r"(b1));
}
__device__ __forceinline__ uint32_t pack2h(float a, float b) {
    __half2 t = __floats2half2_rn(a, b);
    return *reinterpret_cast<uint32_t*>(&t);
}
__device__ __forceinline__ float ex2f(float x) {
    float r;
    asm("ex2.approx.f32 %0, %1;" : "=f"(r) : "f"(x));
    return r;
}

// ---------------------------------------------------------------------------
// prep: fp32 -> fp16 convert (features); fused transpose for w1 AND w2
// ---------------------------------------------------------------------------
__global__ void cvt_k(const float* __restrict__ X, __half* __restrict__ Hi, size_t n)
{
    size_t stride = (size_t)gridDim.x * blockDim.x * 4;
    for (size_t i = ((size_t)blockIdx.x * blockDim.x + threadIdx.x) * 4; i < n; i += stride) {
        float4 v = *(const float4*)(X + i);
        __half h[4] = {__float2half_rn(v.x), __float2half_rn(v.y),
                       __float2half_rn(v.z), __float2half_rn(v.w)};
        *(uint2*)(Hi + i) = *(uint2*)h;
    }
}
// blockIdx.x < 64: w1 [2048 x 2048]; else w2 [2048 x 128]
__global__ void tprep_k(const float* __restrict__ W1, const float* __restrict__ W2,
                        __half* __restrict__ T1, __half* __restrict__ T2)
{
    __shared__ float t[32][33];
    const int bxr = blockIdx.x;
    const float* W;
    __half* T;
    int N, nxb;
    if (bxr < 64) { W = W1; T = T1; N = HH; nxb = bxr; }
    else          { W = W2; T = T2; N = FF; nxb = bxr - 64; }
    const int nx = nxb * 32, ky = blockIdx.y * 32;
    const int tx = threadIdx.x, ty = threadIdx.y;   // 32 x 8
#pragma unroll
    for (int i = 0; i < 4; i++)
        t[ty + 8 * i][tx] = W[(size_t)(ky + ty + 8 * i) * N + nx + tx];
    __syncthreads();
#pragma unroll
    for (int i = 0; i < 4; i++) {
        float v = t[tx][ty + 8 * i];
        T[(size_t)(nx + ty + 8 * i) * KK + ky + tx] = __float2half_rn(v);
    }
}

// ---------------------------------------------------------------------------
// GEMM1: pure fp16. C = relu(A @ B^T + bias). 128x128, Kc=64, 3-stage,
// one sync/iter, uniform group accounting (race-free tail).
// ---------------------------------------------------------------------------
__global__ __launch_bounds__(256, 2)
void hgemm1_k(const __half* __restrict__ Ahi, const __half* __restrict__ Bhi,
              const float* __restrict__ bias, int Nout, __half* __restrict__ Chi)
{
    extern __shared__ char smem[];
    const uint32_t sb = smem_u32(smem);
    const int tid = threadIdx.x;
    const int bx = blockIdx.x, by = blockIdx.y;
    const int lane = tid & 31, warp = tid >> 5;
    const int wm = warp & 1, wn = warp >> 1;
    const int quad = lane >> 3, l8 = lane & 7;

    float* bias_s = (float*)(smem + 98304);
    if (tid < 128) bias_s[tid] = bias[bx * 128 + tid];

    const int lrow = tid >> 1, lhalf = tid & 1;
    const __half* gA0 = Ahi + (size_t)(by * 128 + lrow) * KK;
    const __half* gB0 = Bhi + (size_t)(bx * 128 + lrow) * KK;
    const uint32_t lso = (uint32_t)(lrow >> 3) * 1024 + (lrow & 7) * 16;

    auto load_stage = [&](int kt) {
        uint32_t st = sb + (uint32_t)(kt % 3) * 32768;
        const int kbase = kt * 64;
#pragma unroll
        for (int j = 0; j < 4; j++) {
            int kb = lhalf * 4 + j;
            uint32_t so = lso + (uint32_t)kb * 128;
            cp16(st + so,          gA0 + kbase + kb * 8);
            cp16(st + 16384 + so,  gB0 + kbase + kb * 8);
        }
        CP_COMMIT();
    };

    float acc[4][4][4];
#pragma unroll
    for (int f = 0; f < 4; f++)
#pragma unroll
        for (int n = 0; n < 4; n++)
#pragma unroll
            for (int q = 0; q < 4; q++) acc[f][n][q] = 0.f;

    const uint32_t aoff = (uint32_t)(quad & 1) * 1024 + (uint32_t)(quad >> 1) * 128 + l8 * 16;
    const uint32_t boff = (uint32_t)(quad >> 1) * 1024 + (uint32_t)(quad & 1) * 128 + l8 * 16;

    const int NKT = KK / 64;   // 32
    load_stage(0);
    load_stage(1);
    for (int kt = 0; kt < NKT; kt++) {
        CP_WAIT(1);
        __syncthreads();
        if (kt + 2 < NKT) load_stage(kt + 2);
        else              CP_COMMIT();          // uniform accounting
        const uint32_t st = sb + (uint32_t)(kt % 3) * 32768;
#pragma unroll
        for (int ks = 0; ks < 4; ks++) {
            uint32_t ah[4][4], bh[2][4];
#pragma unroll
            for (int f = 0; f < 4; f++)
                ldsm4(ah[f], st + (uint32_t)(wm * 8 + f * 2) * 1024 + ks * 256 + aoff);
#pragma unroll
            for (int p = 0; p < 2; p++)
                ldsm4(bh[p], st + 16384 + (uint32_t)(wn * 4 + p * 2) * 1024 + ks * 256 + boff);
#pragma unroll
            for (int f = 0; f < 4; f++)
#pragma unroll
                for (int nf = 0; nf < 4; nf++) {
                    int p = nf >> 1, q = (nf & 1) * 2;
                    mma_f16(acc[f][nf], ah[f], bh[p][q], bh[p][q + 1]);
                }
        }
    }

    const int rsub = lane >> 2;
    const int csub = (lane & 3) * 2;
#pragma unroll
    for (int f = 0; f < 4; f++) {
        int r0 = by * 128 + wm * 64 + f * 16 + rsub;
#pragma unroll
        for (int nf = 0; nf < 4; nf++) {
            int cn = wn * 32 + nf * 8 + csub;
            float b0 = bias_s[cn], b1 = bias_s[cn + 1];
            float v00 = fmaxf(acc[f][nf][0] + b0, 0.f);
            float v01 = fmaxf(acc[f][nf][1] + b1, 0.f);
            float v10 = fmaxf(acc[f][nf][2] + b0, 0.f);
            float v11 = fmaxf(acc[f][nf][3] + b1, 0.f);
            size_t o0 = (size_t)r0 * Nout + bx * 128 + cn;
            size_t o1 = o0 + (size_t)8 * Nout;
            *(uint32_t*)(Chi + o0) = pack2h(v00, v01);
            *(uint32_t*)(Chi + o1) = pack2h(v10, v11);
        }
    }
}

// ---------------------------------------------------------------------------
// GEMM2: 64-row tiles, single-term fp16, fused L2-normalize.
// Kc=32, *** 8-stage x 12KB pipeline *** (7-chunk lookahead) to cover DRAM
// latency; uniform commits at the tail.
// ---------------------------------------------------------------------------
__global__ __launch_bounds__(256, 2)
void hgemm2_k(const __half* __restrict__ Ahi, const __half* __restrict__ Bhi,
              const float* __restrict__ bias,
              float* __restrict__ Zf, __half* __restrict__ Zhi,
              float* __restrict__ outz)
{
    extern __shared__ char smem[];
    const uint32_t sb = smem_u32(smem);
    const int tid = threadIdx.x;
    const int by = blockIdx.y;
    const int lane = tid & 31, warp = tid >> 5;
    const int wm = warp & 1, wn = warp >> 1;
    const int quad = lane >> 3, l8 = lane & 7;

    float* bias_s = (float*)(smem + 98304);
    float* rowsq4 = (float*)(smem + 98304 + 512);   // [4][64]
    if (tid < 128) bias_s[tid] = bias[tid];

    const int arow = tid >> 2, akb = tid & 3;
    const uint32_t aso = (uint32_t)(arow >> 3) * 512 + (arow & 7) * 16 + akb * 128;
    const __half* gA0 = Ahi + (size_t)(by * 64 + arow) * KK + akb * 8;
    const int lrow = tid >> 1, lhalf = tid & 1;
    const uint32_t lso = (uint32_t)(lrow >> 3) * 512 + (lrow & 7) * 16;
    const __half* gB0 = Bhi + (size_t)lrow * KK;

    auto load_stage = [&](int kt) {
        uint32_t st = sb + (uint32_t)(kt & 7) * 12288;
        const int kbase = kt * 32;
        cp16(st + aso, gA0 + kbase);
#pragma unroll
        for (int j = 0; j < 2; j++) {
            int kb = lhalf * 2 + j;
            cp16(st + 4096 + lso + (uint32_t)kb * 128, gB0 + kbase + kb * 8);
        }
        CP_COMMIT();
    };

    float acc[2][4][4];
#pragma unroll
    for (int f = 0; f < 2; f++)
#pragma unroll
        for (int n = 0; n < 4; n++)
#pragma unroll
            for (int q = 0; q < 4; q++) acc[f][n][q] = 0.f;

    const uint32_t aoff = (uint32_t)(quad & 1) * 512 + (uint32_t)(quad >> 1) * 128 + l8 * 16;
    const uint32_t boff = (uint32_t)(quad >> 1) * 512 + (uint32_t)(quad & 1) * 128 + l8 * 16;

    const int NKT = KK / 32;   // 64
#pragma unroll
    for (int s = 0; s < 7; s++) load_stage(s);
    for (int kt = 0; kt < NKT; kt++) {
        CP_WAIT(6);
        __syncthreads();
        if (kt + 7 < NKT) load_stage(kt + 7);
        else              CP_COMMIT();          // uniform accounting
        const uint32_t st = sb + (uint32_t)(kt & 7) * 12288;
#pragma unroll
        for (int ks = 0; ks < 2; ks++) {
            uint32_t ah[2][4], bh[2][4];
#pragma unroll
            for (int f = 0; f < 2; f++)
                ldsm4(ah[f], st + (uint32_t)(wm * 4 + f * 2) * 512 + ks * 256 + aoff);
#pragma unroll
            for (int p = 0; p < 2; p++)
                ldsm4(bh[p], st + 4096 + (uint32_t)(wn * 4 + p * 2) * 512 + ks * 256 + boff);
#pragma unroll
            for (int f = 0; f < 2; f++)
#pragma unroll
                for (int nf = 0; nf < 4; nf++) {
                    int p = nf >> 1, q = (nf & 1) * 2;
                    mma_f16(acc[f][nf], ah[f], bh[p][q], bh[p][q + 1]);
                }
        }
    }

    const int rsub = lane >> 2;
    const int csub = (lane & 3) * 2;
#pragma unroll
    for (int f = 0; f < 2; f++) {
        float s0 = 0.f, s1 = 0.f;
#pragma unroll
        for (int nf = 0; nf < 4; nf++) {
            int cn = wn * 32 + nf * 8 + csub;
            float b0 = bias_s[cn], b1 = bias_s[cn + 1];
            float v00 = acc[f][nf][0] + b0, v01 = acc[f][nf][1] + b1;
            float v10 = acc[f][nf][2] + b0, v11 = acc[f][nf][3] + b1;
            s0 += v00 * v00 + v01 * v01;
            s1 += v10 * v10 + v11 * v11;
        }
        s0 += __shfl_xor_sync(0xffffffffu, s0, 1);
        s0 += __shfl_xor_sync(0xffffffffu, s0, 2);
        s1 += __shfl_xor_sync(0xffffffffu, s1, 1);
        s1 += __shfl_xor_sync(0xffffffffu, s1, 2);
        if ((lane & 3) == 0) {
            int lr = wm * 32 + f * 16 + rsub;
            rowsq4[wn * 64 + lr] = s0;
            rowsq4[wn * 64 + lr + 8] = s1;
        }
    }
    __syncthreads();
#pragma unroll
    for (int f = 0; f < 2; f++) {
        int lr0 = wm * 32 + f * 16 + rsub;
        float sq0 = rowsq4[lr0] + rowsq4[64 + lr0] + rowsq4[128 + lr0] + rowsq4[192 + lr0];
        float sq1 = rowsq4[lr0 + 8] + rowsq4[64 + lr0 + 8] + rowsq4[128 + lr0 + 8] + rowsq4[192 + lr0 + 8];
        float inv0 = rsqrtf(fmaxf(sq0, 1e-24f));
        float inv1 = rsqrtf(fmaxf(sq1, 1e-24f));
        int r0 = by * 64 + lr0;
#pragma unroll
        for (int nf = 0; nf < 4; nf++) {
            int cn = wn * 32 + nf * 8 + csub;
            float b0 = bias_s[cn], b1 = bias_s[cn + 1];
            float z00 = (acc[f][nf][0] + b0) * inv0, z01 = (acc[f][nf][1] + b1) * inv0;
            float z10 = (acc[f][nf][2] + b0) * inv1, z11 = (acc[f][nf][3] + b1) * inv1;
            size_t o0 = (size_t)r0 * FF + cn;
            size_t o1 = o0 + (size_t)8 * FF;
            *(float2*)(Zf + o0) = make_float2(z00, z01);
            *(float2*)(Zf + o1) = make_float2(z10, z11);
            if (outz) {   // d_out+1 only 4B aligned: scalar stores
                outz[o0] = z00; outz[o0 + 1] = z01;
                outz[o1] = z10; outz[o1 + 1] = z11;
            }
            *(uint32_t*)(Zhi + o0) = pack2h(z00, z01);
            *(uint32_t*)(Zhi + o1) = pack2h(z10, z11);
        }
    }
}

// ---------------------------------------------------------------------------
// Triangular lse tile kernel (lower triangle, 8256 CTAs): row-sums for by,
// column-sums for bx -> ps[colblk][row]; every slot written exactly once.
// ---------------------------------------------------------------------------
__global__ __launch_bounds__(256, 2)
void lse_tri_k(const __half* __restrict__ Zhi, float* __restrict__ ps)
{
    extern __shared__ char smem[];
    const uint32_t sb = smem_u32(smem);
    float* colarr = (float*)(smem + 65536);   // [2][128]
    float* lsum4  = (float*)(smem + 66560);   // [4][128]

    const int tid = threadIdx.x;
    const int lane = tid & 31, warp = tid >> 5;
    const int wm = warp & 1, wn = warp >> 1;
    const int quad = lane >> 3, l8 = lane & 7;

    const int t = blockIdx.x;
    int by = (int)((sqrtf(8.0f * (float)t + 1.0f) - 1.0f) * 0.5f);
    while ((by + 1) * (by + 2) / 2 <= t) by++;
    while (by * (by + 1) / 2 > t) by--;
    const int bx = t - by * (by + 1) / 2;

    const int lrow = tid >> 1, lhalf = tid & 1;
    const uint32_t lso = (uint32_t)(lrow >> 3) * 2048 + (lrow & 7) * 16;
    {
        const __half* ga = Zhi + (size_t)(by * 128 + lrow) * FF;
        const __half* gb = Zhi + (size_t)(bx * 128 + lrow) * FF;
#pragma unroll
        for (int j = 0; j < 8; j++) {
            int kb = lhalf * 8 + j;
            cp16(sb + lso + kb * 128,         ga + kb * 8);
            cp16(sb + 32768 + lso + kb * 128, gb + kb * 8);
        }
        CP_COMMIT();
    }
    CP_WAIT(0);
    __syncthreads();

    float acc[4][4][4];
#pragma unroll
    for (int f = 0; f < 4; f++)
#pragma unroll
        for (int n = 0; n < 4; n++)
#pragma unroll
            for (int q = 0; q < 4; q++) acc[f][n][q] = 0.f;

    const uint32_t aoff = (uint32_t)(quad & 1) * 2048 + (uint32_t)(quad >> 1) * 128 + l8 * 16;
    const uint32_t boff = (uint32_t)(quad >> 1) * 2048 + (uint32_t)(quad & 1) * 128 + l8 * 16;

#pragma unroll
    for (int ks = 0; ks < 8; ks++) {
        uint32_t ah[4][4], bh[2][4];
#pragma unroll
        for (int f = 0; f < 4; f++)
            ldsm4(ah[f], sb + (uint32_t)(wm * 8 + f * 2) * 2048 + ks * 256 + aoff);
#pragma unroll
        for (int p = 0; p < 2; p++)
            ldsm4(bh[p], sb + 32768 + (uint32_t)(wn * 4 + p * 2) * 2048 + ks * 256 + boff);
#pragma unroll
        for (int f = 0; f < 4; f++)
#pragma unroll
            for (int nf = 0; nf < 4; nf++) {
                int p = nf >> 1, q = (nf & 1) * 2;
                mma_f16(acc[f][nf], ah[f], bh[p][q], bh[p][q + 1]);
            }
    }

    const int rsub = lane >> 2;
    const int csub = (lane & 3) * 2;
    const bool diag = (by == bx);

    float rs[4][2];
    float colp[4][2];
#pragma unroll
    for (int f = 0; f < 4; f++) { rs[f][0] = 0.f; rs[f][1] = 0.f; }
#pragma unroll
    for (int nf = 0; nf < 4; nf++) { colp[nf][0] = 0.f; colp[nf][1] = 0.f; }

#pragma unroll
    for (int f = 0; f < 4; f++) {
#pragma unroll
        for (int nf = 0; nf < 4; nf++) {
            float e00 = ex2f(fmaf(acc[f][nf][0], C_EX2, -C_EX2));
            float e01 = ex2f(fmaf(acc[f][nf][1], C_EX2, -C_EX2));
            float e10 = ex2f(fmaf(acc[f][nf][2], C_EX2, -C_EX2));
            float e11 = ex2f(fmaf(acc[f][nf][3], C_EX2, -C_EX2));
            if (diag) {
                int lr = wm * 64 + f * 16 + rsub;
                int lc = wn * 32 + nf * 8 + csub;
                if (lr == lc)         e00 = 0.f;
                if (lr == lc + 1)     e01 = 0.f;
                if (lr + 8 == lc)     e10 = 0.f;
                if (lr + 8 == lc + 1) e11 = 0.f;
            }
            rs[f][0] += e00 + e01;
            rs[f][1] += e10 + e11;
            colp[nf][0] += e00 + e10;
            colp[nf][1] += e01 + e11;
        }
    }

#pragma unroll
    for (int f = 0; f < 4; f++) {
#pragma unroll
        for (int h = 0; h < 2; h++) {
            float v = rs[f][h];
            v += __shfl_xor_sync(0xffffffffu, v, 1);
            v += __shfl_xor_sync(0xffffffffu, v, 2);
            if ((lane & 3) == 0)
                lsum4[wn * 128 + wm * 64 + f * 16 + h * 8 + rsub] = v;
        }
    }
#pragma unroll
    for (int nf = 0; nf < 4; nf++) {
#pragma unroll
        for (int h = 0; h < 2; h++) {
            float v = colp[nf][h];
            v += __shfl_xor_sync(0xffffffffu, v, 4);
            v += __shfl_xor_sync(0xffffffffu, v, 8);
            v += __shfl_xor_sync(0xffffffffu, v, 16);
            if (lane < 4)
                colarr[wm * 128 + wn * 32 + nf * 8 + lane * 2 + h] = v;
        }
    }
    __syncthreads();
    if (tid < 128) {
        float rtot = lsum4[tid] + lsum4[128 + tid] + lsum4[256 + tid] + lsum4[384 + tid];
        ps[(size_t)bx * MB + by * 128 + tid] = rtot;
        if (!diag) {
            float ctot = colarr[tid] + colarr[128 + tid];
            ps[(size_t)by * MB + bx * 128 + tid] = ctot;
        }
    }
}

// ---------------------------------------------------------------------------
__global__ void sumps_k(const float* __restrict__ ps, float* __restrict__ lse)
{
    const int row = blockIdx.x * 256 + threadIdx.x;
    float tot = 0.f;
#pragma unroll 8
    for (int c = 0; c < 128; c++) tot += ps[(size_t)c * MB + row];
    lse[row] = logf(tot) + INV_T;
}

__global__ void pos_k(const float* __restrict__ Z, float* __restrict__ pos)
{
    const int row = blockIdx.x;
    const int t = threadIdx.x;
    const int prow = (row + MB / 2) & (MB - 1);
    float s = Z[(size_t)row * FF + t] * Z[(size_t)prow * FF + t];
#pragma unroll
    for (int o = 16; o; o >>= 1) s += __shfl_xor_sync(0xffffffffu, s, o);
    __shared__ float ws[4];
    if ((t & 31) == 0) ws[t >> 5] = s;
    __syncthreads();
    if (t == 0) pos[row] = (ws[0] + ws[1] + ws[2] + ws[3]) * INV_T;
}

__global__ void loss_k(const float* __restrict__ lse, const float* __restrict__ pos,
                       float* __restrict__ out)
{
    __shared__ float sm[256];
    const int t = threadIdx.x;
    float s = 0.f;
    for (int i = t; i < MB; i += 256) s += lse[i] - pos[i];
    sm[t] = s;
    __syncthreads();
    for (int o = 128; o; o >>= 1) {
        if (t < o) sm[t] += sm[t + o];
        __syncthreads();
    }
    if (t == 0) out[0] = sm[0] * (1.0f / MB);
}

// ---------------------------------------------------------------------------
extern "C" void kernel_launch(void* const* d_in, const int* in_sizes, int n_in,
                              void* d_out, int out_size)
{
    const float* features = (const float*)d_in[0];
    const float* w1 = (const float*)d_in[1];
    const float* b1 = (const float*)d_in[2];
    const float* w2 = (const float*)d_in[3];
    const float* b2 = (const float*)d_in[4];
    float* out = (float*)d_out;

    __half *fhi, *w1hi, *w2hi, *hhi, *zhi;
    float *z, *psb, *lseb, *posb;
    cudaGetSymbolAddress((void**)&fhi,  g_fhi);
    cudaGetSymbolAddress((void**)&w1hi, g_w1hi);
    cudaGetSymbolAddress((void**)&w2hi, g_w2hi);
    cudaGetSymbolAddress((void**)&hhi,  g_hhi);
    cudaGetSymbolAddress((void**)&zhi,  g_zhi);
    cudaGetSymbolAddress((void**)&z,    g_z);
    cudaGetSymbolAddress((void**)&psb,  g_ps);
    cudaGetSymbolAddress((void**)&lseb, g_lse);
    cudaGetSymbolAddress((void**)&posb, g_pos);

    const int SM_G1 = 98304 + 512;           // 3 stages x 32KB + bias
    const int SM_G2 = 98304 + 512 + 1024;    // 8 stages x 12KB + bias + rowsq
    const int SM_L  = 65536 + 1024 + 2048;   // A + B + colarr + lsum
    cudaFuncSetAttribute(hgemm1_k, cudaFuncAttributeMaxDynamicSharedMemorySize, SM_G1);
    cudaFuncSetAttribute(hgemm2_k, cudaFuncAttributeMaxDynamicSharedMemorySize, SM_G2);
    cudaFuncSetAttribute(lse_tri_k, cudaFuncAttributeMaxDynamicSharedMemorySize, SM_L);

    // prep
    cvt_k<<<2048, 256>>>(features, fhi, (size_t)MB * DD);
    tprep_k<<<dim3(64 + FF / 32, KK / 32), dim3(32, 8)>>>(w1, w2, w1hi, w2hi);

    // 1) h = relu(features @ w1 + b1)
    hgemm1_k<<<dim3(HH / 128, MB / 128), 256, SM_G1>>>(fhi, w1hi, b1, HH, hhi);

    // 2) p = h @ w2 + b2, fused L2-normalize
    float* outz = (out_size >= 1 + MB * FF) ? (out + 1) : nullptr;
    hgemm2_k<<<dim3(1, MB / 64), 256, SM_G2>>>(hhi, w2hi, b2, z, zhi, outz);

    // 3) pos
    pos_k<<<MB, 128>>>(z, posb);

    // 4) triangular masked exp-sum tiles
    const int NTRI = (MB / 128) * (MB / 128 + 1) / 2;   // 8256
    lse_tri_k<<<NTRI, 256, SM_L>>>(zhi, psb);

    // 5) combine partials -> lse, 6) loss
    sumps_k<<<MB / 256, 256>>>(psb, lseb);
    loss_k<<<1, 256>>>(lseb, posb, out);
}

// round 15
// speedup vs baseline: 1.0305x; 1.0305x over previous
#include <cuda_runtime.h>
#include <cuda_fp16.h>
#include <math.h>
#include <stdint.h>

#define MB 16384   // rows (2N)
#define DD 2048
#define HH 2048
#define FF 128
#define KK 2048    // K of both big GEMMs

constexpr float INV_T = 1.0f / 0.07f;
constexpr float C_EX2 = 20.6099773964f;   // INV_T * log2(e)

// ---------------- scratch --------------------------------------------------
__device__ __half g_fhi [(size_t)MB * DD];
__device__ __half g_w1hi[(size_t)HH * DD];
__device__ __half g_w2hi[(size_t)FF * HH];
__device__ __half g_hhi [(size_t)MB * HH];
__device__ __half g_zhi [(size_t)MB * FF];
__device__ float g_z  [(size_t)MB * FF];
__device__ float g_ps [(size_t)128 * MB];   // 8MB partial exp-sums [colblk][row]
__device__ float g_lse[MB];
__device__ float g_pos[MB];

// ---------------- helpers ---------------------------------------------------
__device__ __forceinline__ uint32_t smem_u32(const void* p) {
    uint32_t a;
    asm("{ .reg .u64 t; cvta.to.shared.u64 t, %1; cvt.u32.u64 %0, t; }"
        : "=r"(a) : "l"(p));
    return a;
}
__device__ __forceinline__ void cp16(uint32_t s, const void* g) {
    asm volatile("cp.async.cg.shared.global [%0], [%1], 16;" :: "r"(s), "l"(g));
}
#define CP_COMMIT() asm volatile("cp.async.commit_group;")
#define CP_WAIT(n)  asm volatile("cp.async.wait_group %0;" :: "n"(n))

__device__ __forceinline__ void ldsm4(uint32_t* r, uint32_t a) {
    asm volatile("ldmatrix.sync.aligned.m8n8.x4.shared.b16 {%0,%1,%2,%3}, [%4];"
                 : "=r"(r[0]), "=r"(r[1]), "=r"(r[2]), "=r"(r[3]) : "r"(a));
}
__device__ __forceinline__ void mma_f16(float* c, const uint32_t* a,
                                        uint32_t b0, uint32_t b1) {
    asm volatile(
        "mma.sync.aligned.m16n8k16.row.col.f32.f16.f16.f32 "
        "{%0,%1,%2,%3}, {%4,%5,%6,%7}, {%8,%9}, {%0,%1,%2,%3};"
        : "+f"(c[0]), "+f"(c[1]), "+f"(c[2]), "+f"(c[3])
        : "r"(a[0]), "r"(a[1]), "r"(a[2]), "r"(a[3]), "r"(b0), "r"(b1));
}
__device__ __forceinline__ uint32_t pack2h(float a, float b) {
    __half2 t = __floats2half2_rn(a, b);
    return *reinterpret_cast<uint32_t*>(&t);
}
__device__ __forceinline__ float ex2f(float x) {
    float r;
    asm("ex2.approx.f32 %0, %1;" : "=f"(r) : "f"(x));
    return r;
}

// ---------------------------------------------------------------------------
// prep: fp32 -> fp16 convert (features); fused transpose for w1 AND w2
// ---------------------------------------------------------------------------
__global__ void cvt_k(const float* __restrict__ X, __half* __restrict__ Hi, size_t n)
{
    size_t stride = (size_t)gridDim.x * blockDim.x * 4;
    for (size_t i = ((size_t)blockIdx.x * blockDim.x + threadIdx.x) * 4; i < n; i += stride) {
        float4 v = *(const float4*)(X + i);
        __half h[4] = {__float2half_rn(v.x), __float2half_rn(v.y),
                       __float2half_rn(v.z), __float2half_rn(v.w)};
        *(uint2*)(Hi + i) = *(uint2*)h;
    }
}
// blockIdx.x < 64: w1 [2048 x 2048]; else w2 [2048 x 128]
__global__ void tprep_k(const float* __restrict__ W1, const float* __restrict__ W2,
                        __half* __restrict__ T1, __half* __restrict__ T2)
{
    __shared__ float t[32][33];
    const int bxr = blockIdx.x;
    const float* W;
    __half* T;
    int N, nxb;
    if (bxr < 64) { W = W1; T = T1; N = HH; nxb = bxr; }
    else          { W = W2; T = T2; N = FF; nxb = bxr - 64; }
    const int nx = nxb * 32, ky = blockIdx.y * 32;
    const int tx = threadIdx.x, ty = threadIdx.y;   // 32 x 8
#pragma unroll
    for (int i = 0; i < 4; i++)
        t[ty + 8 * i][tx] = W[(size_t)(ky + ty + 8 * i) * N + nx + tx];
    __syncthreads();
#pragma unroll
    for (int i = 0; i < 4; i++) {
        float v = t[tx][ty + 8 * i];
        T[(size_t)(nx + ty + 8 * i) * KK + ky + tx] = __float2half_rn(v);
    }
}

// ---------------------------------------------------------------------------
// GEMM1: pure fp16, 256x128 CTA tile, 512 threads (16 warps, 4x4), 1 CTA/SM.
// Kc=64, 3-stage x 48KB (144KB smem), one sync/iter, uniform tail commits.
// 25% less L2 operand traffic per MAC than the 128x128 version.
// ---------------------------------------------------------------------------
__global__ __launch_bounds__(512, 1)
void hgemm1_k(const __half* __restrict__ Ahi, const __half* __restrict__ Bhi,
              const float* __restrict__ bias, int Nout, __half* __restrict__ Chi)
{
    extern __shared__ char smem[];
    const uint32_t sb = smem_u32(smem);
    const int tid = threadIdx.x;
    const int bx = blockIdx.x, by = blockIdx.y;
    const int lane = tid & 31, warp = tid >> 5;
    const int wm = warp & 3, wn = warp >> 2;        // 4 x 4 warp grid
    const int quad = lane >> 3, l8 = lane & 7;

    float* bias_s = (float*)(smem + 147456);
    if (tid < 128) bias_s[tid] = bias[bx * 128 + tid];

    // A loader: 256 rows x 8 kb-chunks; 2 threads/row, 4 cp16 each
    const int arow = tid >> 1, ah4 = (tid & 1) * 4;
    const __half* gA0 = Ahi + (size_t)(by * 256 + arow) * KK;
    const uint32_t aslo = (uint32_t)(arow >> 3) * 1024 + (arow & 7) * 16;
    // B loader: 128 rows x 8 kb-chunks; 4 threads/row, 2 cp16 each
    const int brow = tid >> 2, bh2 = (tid & 3) * 2;
    const __half* gB0 = Bhi + (size_t)(bx * 128 + brow) * KK;
    const uint32_t bslo = (uint32_t)(brow >> 3) * 1024 + (brow & 7) * 16;

    auto load_stage = [&](int kt) {
        uint32_t st = sb + (uint32_t)(kt % 3) * 49152;
        const int kbase = kt * 64;
#pragma unroll
        for (int j = 0; j < 4; j++) {
            int kb = ah4 + j;
            cp16(st + aslo + (uint32_t)kb * 128, gA0 + kbase + kb * 8);
        }
#pragma unroll
        for (int j = 0; j < 2; j++) {
            int kb = bh2 + j;
            cp16(st + 32768 + bslo + (uint32_t)kb * 128, gB0 + kbase + kb * 8);
        }
        CP_COMMIT();
    };

    float acc[4][4][4];
#pragma unroll
    for (int f = 0; f < 4; f++)
#pragma unroll
        for (int n = 0; n < 4; n++)
#pragma unroll
            for (int q = 0; q < 4; q++) acc[f][n][q] = 0.f;

    const uint32_t aoff = (uint32_t)(quad & 1) * 1024 + (uint32_t)(quad >> 1) * 128 + l8 * 16;
    const uint32_t boff = (uint32_t)(quad >> 1) * 1024 + (uint32_t)(quad & 1) * 128 + l8 * 16;

    const int NKT = KK / 64;   // 32
    load_stage(0);
    load_stage(1);
    for (int kt = 0; kt < NKT; kt++) {
        CP_WAIT(1);
        __syncthreads();
        if (kt + 2 < NKT) load_stage(kt + 2);
        else              CP_COMMIT();          // uniform accounting (no tail race)
        const uint32_t st = sb + (uint32_t)(kt % 3) * 49152;
#pragma unroll
        for (int ks = 0; ks < 4; ks++) {
            uint32_t ah[4][4], bh[2][4];
#pragma unroll
            for (int f = 0; f < 4; f++)
                ldsm4(ah[f], st + (uint32_t)(wm * 8 + f * 2) * 1024 + ks * 256 + aoff);
#pragma unroll
            for (int p = 0; p < 2; p++)
                ldsm4(bh[p], st + 32768 + (uint32_t)(wn * 4 + p * 2) * 1024 + ks * 256 + boff);
#pragma unroll
            for (int f = 0; f < 4; f++)
#pragma unroll
                for (int nf = 0; nf < 4; nf++) {
                    int p = nf >> 1, q = (nf & 1) * 2;
                    mma_f16(acc[f][nf], ah[f], bh[p][q], bh[p][q + 1]);
                }
        }
    }

    const int rsub = lane >> 2;
    const int csub = (lane & 3) * 2;
#pragma unroll
    for (int f = 0; f < 4; f++) {
        int r0 = by * 256 + wm * 64 + f * 16 + rsub;
#pragma unroll
        for (int nf = 0; nf < 4; nf++) {
            int cn = wn * 32 + nf * 8 + csub;
            float b0 = bias_s[cn], b1 = bias_s[cn + 1];
            float v00 = fmaxf(acc[f][nf][0] + b0, 0.f);
            float v01 = fmaxf(acc[f][nf][1] + b1, 0.f);
            float v10 = fmaxf(acc[f][nf][2] + b0, 0.f);
            float v11 = fmaxf(acc[f][nf][3] + b1, 0.f);
            size_t o0 = (size_t)r0 * Nout + bx * 128 + cn;
            size_t o1 = o0 + (size_t)8 * Nout;
            *(uint32_t*)(Chi + o0) = pack2h(v00, v01);
            *(uint32_t*)(Chi + o1) = pack2h(v10, v11);
        }
    }
}

// ---------------------------------------------------------------------------
// GEMM2: 64-row tiles, single-term fp16, fused L2-normalize.
// Kc=32, 4-stage x 12KB (R13 config), uniform commits.
// ---------------------------------------------------------------------------
__global__ __launch_bounds__(256, 2)
void hgemm2_k(const __half* __restrict__ Ahi, const __half* __restrict__ Bhi,
              const float* __restrict__ bias,
              float* __restrict__ Zf, __half* __restrict__ Zhi,
              float* __restrict__ outz)
{
    extern __shared__ char smem[];
    const uint32_t sb = smem_u32(smem);
    const int tid = threadIdx.x;
    const int by = blockIdx.y;
    const int lane = tid & 31, warp = tid >> 5;
    const int wm = warp & 1, wn = warp >> 1;
    const int quad = lane >> 3, l8 = lane & 7;

    float* bias_s = (float*)(smem + 49152);
    float* rowsq4 = (float*)(smem + 49152 + 512);   // [4][64]
    if (tid < 128) bias_s[tid] = bias[tid];

    const int arow = tid >> 2, akb = tid & 3;
    const uint32_t aso = (uint32_t)(arow >> 3) * 512 + (arow & 7) * 16 + akb * 128;
    const __half* gA0 = Ahi + (size_t)(by * 64 + arow) * KK + akb * 8;
    const int lrow = tid >> 1, lhalf = tid & 1;
    const uint32_t lso = (uint32_t)(lrow >> 3) * 512 + (lrow & 7) * 16;
    const __half* gB0 = Bhi + (size_t)lrow * KK;

    auto load_stage = [&](int kt) {
        uint32_t st = sb + (uint32_t)(kt & 3) * 12288;
        const int kbase = kt * 32;
        cp16(st + aso, gA0 + kbase);
#pragma unroll
        for (int j = 0; j < 2; j++) {
            int kb = lhalf * 2 + j;
            cp16(st + 4096 + lso + (uint32_t)kb * 128, gB0 + kbase + kb * 8);
        }
        CP_COMMIT();
    };

    float acc[2][4][4];
#pragma unroll
    for (int f = 0; f < 2; f++)
#pragma unroll
        for (int n = 0; n < 4; n++)
#pragma unroll
            for (int q = 0; q < 4; q++) acc[f][n][q] = 0.f;

    const uint32_t aoff = (uint32_t)(quad & 1) * 512 + (uint32_t)(quad >> 1) * 128 + l8 * 16;
    const uint32_t boff = (uint32_t)(quad >> 1) * 512 + (uint32_t)(quad & 1) * 128 + l8 * 16;

    const int NKT = KK / 32;
    load_stage(0); load_stage(1); load_stage(2);
    for (int kt = 0; kt < NKT; kt++) {
        CP_WAIT(2);
        __syncthreads();
        if (kt + 3 < NKT) load_stage(kt + 3);
        else              CP_COMMIT();          // uniform accounting
        const uint32_t st = sb + (uint32_t)(kt & 3) * 12288;
#pragma unroll
        for (int ks = 0; ks < 2; ks++) {
            uint32_t ah[2][4], bh[2][4];
#pragma unroll
            for (int f = 0; f < 2; f++)
                ldsm4(ah[f], st + (uint32_t)(wm * 4 + f * 2) * 512 + ks * 256 + aoff);
#pragma unroll
            for (int p = 0; p < 2; p++)
                ldsm4(bh[p], st + 4096 + (uint32_t)(wn * 4 + p * 2) * 512 + ks * 256 + boff);
#pragma unroll
            for (int f = 0; f < 2; f++)
#pragma unroll
                for (int nf = 0; nf < 4; nf++) {
                    int p = nf >> 1, q = (nf & 1) * 2;
                    mma_f16(acc[f][nf], ah[f], bh[p][q], bh[p][q + 1]);
                }
        }
    }

    const int rsub = lane >> 2;
    const int csub = (lane & 3) * 2;
#pragma unroll
    for (int f = 0; f < 2; f++) {
        float s0 = 0.f, s1 = 0.f;
#pragma unroll
        for (int nf = 0; nf < 4; nf++) {
            int cn = wn * 32 + nf * 8 + csub;
            float b0 = bias_s[cn], b1 = bias_s[cn + 1];
            float v00 = acc[f][nf][0] + b0, v01 = acc[f][nf][1] + b1;
            float v10 = acc[f][nf][2] + b0, v11 = acc[f][nf][3] + b1;
            s0 += v00 * v00 + v01 * v01;
            s1 += v10 * v10 + v11 * v11;
        }
        s0 += __shfl_xor_sync(0xffffffffu, s0, 1);
        s0 += __shfl_xor_sync(0xffffffffu, s0, 2);
        s1 += __shfl_xor_sync(0xffffffffu, s1, 1);
        s1 += __shfl_xor_sync(0xffffffffu, s1, 2);
        if ((lane & 3) == 0) {
            int lr = wm * 32 + f * 16 + rsub;
            rowsq4[wn * 64 + lr] = s0;
            rowsq4[wn * 64 + lr + 8] = s1;
        }
    }
    __syncthreads();
#pragma unroll
    for (int f = 0; f < 2; f++) {
        int lr0 = wm * 32 + f * 16 + rsub;
        float sq0 = rowsq4[lr0] + rowsq4[64 + lr0] + rowsq4[128 + lr0] + rowsq4[192 + lr0];
        float sq1 = rowsq4[lr0 + 8] + rowsq4[64 + lr0 + 8] + rowsq4[128 + lr0 + 8] + rowsq4[192 + lr0 + 8];
        float inv0 = rsqrtf(fmaxf(sq0, 1e-24f));
        float inv1 = rsqrtf(fmaxf(sq1, 1e-24f));
        int r0 = by * 64 + lr0;
#pragma unroll
        for (int nf = 0; nf < 4; nf++) {
            int cn = wn * 32 + nf * 8 + csub;
            float b0 = bias_s[cn], b1 = bias_s[cn + 1];
            float z00 = (acc[f][nf][0] + b0) * inv0, z01 = (acc[f][nf][1] + b1) * inv0;
            float z10 = (acc[f][nf][2] + b0) * inv1, z11 = (acc[f][nf][3] + b1) * inv1;
            size_t o0 = (size_t)r0 * FF + cn;
            size_t o1 = o0 + (size_t)8 * FF;
            *(float2*)(Zf + o0) = make_float2(z00, z01);
            *(float2*)(Zf + o1) = make_float2(z10, z11);
            if (outz) {   // d_out+1 only 4B aligned: scalar stores
                outz[o0] = z00; outz[o0 + 1] = z01;
                outz[o1] = z10; outz[o1 + 1] = z11;
            }
            *(uint32_t*)(Zhi + o0) = pack2h(z00, z01);
            *(uint32_t*)(Zhi + o1) = pack2h(z10, z11);
        }
    }
}

// ---------------------------------------------------------------------------
// Triangular lse tile kernel (lower triangle, 8256 CTAs): row-sums for by,
// column-sums for bx -> ps[colblk][row]; every slot written exactly once.
// ---------------------------------------------------------------------------
__global__ __launch_bounds__(256, 2)
void lse_tri_k(const __half* __restrict__ Zhi, float* __restrict__ ps)
{
    extern __shared__ char smem[];
    const uint32_t sb = smem_u32(smem);
    float* colarr = (float*)(smem + 65536);   // [2][128]
    float* lsum4  = (float*)(smem + 66560);   // [4][128]

    const int tid = threadIdx.x;
    const int lane = tid & 31, warp = tid >> 5;
    const int wm = warp & 1, wn = warp >> 1;
    const int quad = lane >> 3, l8 = lane & 7;

    const int t = blockIdx.x;
    int by = (int)((sqrtf(8.0f * (float)t + 1.0f) - 1.0f) * 0.5f);
    while ((by + 1) * (by + 2) / 2 <= t) by++;
    while (by * (by + 1) / 2 > t) by--;
    const int bx = t - by * (by + 1) / 2;

    const int lrow = tid >> 1, lhalf = tid & 1;
    const uint32_t lso = (uint32_t)(lrow >> 3) * 2048 + (lrow & 7) * 16;
    {
        const __half* ga = Zhi + (size_t)(by * 128 + lrow) * FF;
        const __half* gb = Zhi + (size_t)(bx * 128 + lrow) * FF;
#pragma unroll
        for (int j = 0; j < 8; j++) {
            int kb = lhalf * 8 + j;
            cp16(sb + lso + kb * 128,         ga + kb * 8);
            cp16(sb + 32768 + lso + kb * 128, gb + kb * 8);
        }
        CP_COMMIT();
    }
    CP_WAIT(0);
    __syncthreads();

    float acc[4][4][4];
#pragma unroll
    for (int f = 0; f < 4; f++)
#pragma unroll
        for (int n = 0; n < 4; n++)
#pragma unroll
            for (int q = 0; q < 4; q++) acc[f][n][q] = 0.f;

    const uint32_t aoff = (uint32_t)(quad & 1) * 2048 + (uint32_t)(quad >> 1) * 128 + l8 * 16;
    const uint32_t boff = (uint32_t)(quad >> 1) * 2048 + (uint32_t)(quad & 1) * 128 + l8 * 16;

#pragma unroll
    for (int ks = 0; ks < 8; ks++) {
        uint32_t ah[4][4], bh[2][4];
#pragma unroll
        for (int f = 0; f < 4; f++)
            ldsm4(ah[f], sb + (uint32_t)(wm * 8 + f * 2) * 2048 + ks * 256 + aoff);
#pragma unroll
        for (int p = 0; p < 2; p++)
            ldsm4(bh[p], sb + 32768 + (uint32_t)(wn * 4 + p * 2) * 2048 + ks * 256 + boff);
#pragma unroll
        for (int f = 0; f < 4; f++)
#pragma unroll
            for (int nf = 0; nf < 4; nf++) {
                int p = nf >> 1, q = (nf & 1) * 2;
                mma_f16(acc[f][nf], ah[f], bh[p][q], bh[p][q + 1]);
            }
    }

    const int rsub = lane >> 2;
    const int csub = (lane & 3) * 2;
    const bool diag = (by == bx);

    float rs[4][2];
    float colp[4][2];
#pragma unroll
    for (int f = 0; f < 4; f++) { rs[f][0] = 0.f; rs[f][1] = 0.f; }
#pragma unroll
    for (int nf = 0; nf < 4; nf++) { colp[nf][0] = 0.f; colp[nf][1] = 0.f; }

#pragma unroll
    for (int f = 0; f < 4; f++) {
#pragma unroll
        for (int nf = 0; nf < 4; nf++) {
            float e00 = ex2f(fmaf(acc[f][nf][0], C_EX2, -C_EX2));
            float e01 = ex2f(fmaf(acc[f][nf][1], C_EX2, -C_EX2));
            float e10 = ex2f(fmaf(acc[f][nf][2], C_EX2, -C_EX2));
            float e11 = ex2f(fmaf(acc[f][nf][3], C_EX2, -C_EX2));
            if (diag) {
                int lr = wm * 64 + f * 16 + rsub;
                int lc = wn * 32 + nf * 8 + csub;
                if (lr == lc)         e00 = 0.f;
                if (lr == lc + 1)     e01 = 0.f;
                if (lr + 8 == lc)     e10 = 0.f;
                if (lr + 8 == lc + 1) e11 = 0.f;
            }
            rs[f][0] += e00 + e01;
            rs[f][1] += e10 + e11;
            colp[nf][0] += e00 + e10;
            colp[nf][1] += e01 + e11;
        }
    }

#pragma unroll
    for (int f = 0; f < 4; f++) {
#pragma unroll
        for (int h = 0; h < 2; h++) {
            float v = rs[f][h];
            v += __shfl_xor_sync(0xffffffffu, v, 1);
            v += __shfl_xor_sync(0xffffffffu, v, 2);
            if ((lane & 3) == 0)
                lsum4[wn * 128 + wm * 64 + f * 16 + h * 8 + rsub] = v;
        }
    }
#pragma unroll
    for (int nf = 0; nf < 4; nf++) {
#pragma unroll
        for (int h = 0; h < 2; h++) {
            float v = colp[nf][h];
            v += __shfl_xor_sync(0xffffffffu, v, 4);
            v += __shfl_xor_sync(0xffffffffu, v, 8);
            v += __shfl_xor_sync(0xffffffffu, v, 16);
            if (lane < 4)
                colarr[wm * 128 + wn * 32 + nf * 8 + lane * 2 + h] = v;
        }
    }
    __syncthreads();
    if (tid < 128) {
        float rtot = lsum4[tid] + lsum4[128 + tid] + lsum4[256 + tid] + lsum4[384 + tid];
        ps[(size_t)bx * MB + by * 128 + tid] = rtot;
        if (!diag) {
            float ctot = colarr[tid] + colarr[128 + tid];
            ps[(size_t)by * MB + bx * 128 + tid] = ctot;
        }
    }
}

// ---------------------------------------------------------------------------
__global__ void sumps_k(const float* __restrict__ ps, float* __restrict__ lse)
{
    const int row = blockIdx.x * 256 + threadIdx.x;
    float tot = 0.f;
#pragma unroll 8
    for (int c = 0; c < 128; c++) tot += ps[(size_t)c * MB + row];
    lse[row] = logf(tot) + INV_T;
}

__global__ void pos_k(const float* __restrict__ Z, float* __restrict__ pos)
{
    const int row = blockIdx.x;
    const int t = threadIdx.x;
    const int prow = (row + MB / 2) & (MB - 1);
    float s = Z[(size_t)row * FF + t] * Z[(size_t)prow * FF + t];
#pragma unroll
    for (int o = 16; o; o >>= 1) s += __shfl_xor_sync(0xffffffffu, s, o);
    __shared__ float ws[4];
    if ((t & 31) == 0) ws[t >> 5] = s;
    __syncthreads();
    if (t == 0) pos[row] = (ws[0] + ws[1] + ws[2] + ws[3]) * INV_T;
}

__global__ void loss_k(const float* __restrict__ lse, const float* __restrict__ pos,
                       float* __restrict__ out)
{
    __shared__ float sm[256];
    const int t = threadIdx.x;
    float s = 0.f;
    for (int i = t; i < MB; i += 256) s += lse[i] - pos[i];
    sm[t] = s;
    __syncthreads();
    for (int o = 128; o; o >>= 1) {
        if (t < o) sm[t] += sm[t + o];
        __syncthreads();
    }
    if (t == 0) out[0] = sm[0] * (1.0f / MB);
}

// ---------------------------------------------------------------------------
extern "C" void kernel_launch(void* const* d_in, const int* in_sizes, int n_in,
                              void* d_out, int out_size)
{
    const float* features = (const float*)d_in[0];
    const float* w1 = (const float*)d_in[1];
    const float* b1 = (const float*)d_in[2];
    const float* w2 = (const float*)d_in[3];
    const float* b2 = (const float*)d_in[4];
    float* out = (float*)d_out;

    __half *fhi, *w1hi, *w2hi, *hhi, *zhi;
    float *z, *psb, *lseb, *posb;
    cudaGetSymbolAddress((void**)&fhi,  g_fhi);
    cudaGetSymbolAddress((void**)&w1hi, g_w1hi);
    cudaGetSymbolAddress((void**)&w2hi, g_w2hi);
    cudaGetSymbolAddress((void**)&hhi,  g_hhi);
    cudaGetSymbolAddress((void**)&zhi,  g_zhi);
    cudaGetSymbolAddress((void**)&z,    g_z);
    cudaGetSymbolAddress((void**)&psb,  g_ps);
    cudaGetSymbolAddress((void**)&lseb, g_lse);
    cudaGetSymbolAddress((void**)&posb, g_pos);

    const int SM_G1 = 147456 + 512;          // 3 stages x 48KB + bias (1 CTA/SM)
    const int SM_G2 = 49152 + 512 + 1024;    // 4 stages x 12KB + bias + rowsq
    const int SM_L  = 65536 + 1024 + 2048;   // A + B + colarr + lsum
    cudaFuncSetAttribute(hgemm1_k, cudaFuncAttributeMaxDynamicSharedMemorySize, SM_G1);
    cudaFuncSetAttribute(hgemm2_k, cudaFuncAttributeMaxDynamicSharedMemorySize, SM_G2);
    cudaFuncSetAttribute(lse_tri_k, cudaFuncAttributeMaxDynamicSharedMemorySize, SM_L);

    // prep
    cvt_k<<<2048, 256>>>(features, fhi, (size_t)MB * DD);
    tprep_k<<<dim3(64 + FF / 32, KK / 32), dim3(32, 8)>>>(w1, w2, w1hi, w2hi);

    // 1) h = relu(features @ w1 + b1)   (256x128 tiles, 512 threads)
    hgemm1_k<<<dim3(HH / 128, MB / 256), 512, SM_G1>>>(fhi, w1hi, b1, HH, hhi);

    // 2) p = h @ w2 + b2, fused L2-normalize
    float* outz = (out_size >= 1 + MB * FF) ? (out + 1) : nullptr;
    hgemm2_k<<<dim3(1, MB / 64), 256, SM_G2>>>(hhi, w2hi, b2, z, zhi, outz);

    // 3) pos
    pos_k<<<MB, 128>>>(z, posb);

    // 4) triangular masked exp-sum tiles
    const int NTRI = (MB / 128) * (MB / 128 + 1) / 2;   // 8256
    lse_tri_k<<<NTRI, 256, SM_L>>>(zhi, psb);

    // 5) combine partials -> lse, 6) loss
    sumps_k<<<MB / 256, 256>>>(psb, lseb);
    loss_k<<<1, 256>>>(lseb, posb, out);
}

// round 16
// speedup vs baseline: 1.0406x; 1.0098x over previous
#include <cuda_runtime.h>
#include <cuda_fp16.h>
#include <math.h>
#include <stdint.h>

#define MB 16384   // rows (2N)
#define DD 2048
#define HH 2048
#define FF 128
#define KK 2048    // K of both big GEMMs

constexpr float INV_T = 1.0f / 0.07f;
constexpr float C_EX2 = 20.6099773964f;   // INV_T * log2(e)

// ---------------- scratch --------------------------------------------------
__device__ __half g_fhi [(size_t)MB * DD];
__device__ __half g_w1hi[(size_t)HH * DD];
__device__ __half g_w2hi[(size_t)FF * HH];
__device__ __half g_hhi [(size_t)MB * HH];
__device__ __half g_zhi [(size_t)MB * FF];
__device__ float g_z  [(size_t)MB * FF];
__device__ float g_p4 [(size_t)4 * MB * FF];   // 32MB split-K partials
__device__ float g_ps [(size_t)128 * MB];      // 8MB partial exp-sums
__device__ float g_lse[MB];
__device__ float g_pos[MB];

// ---------------- helpers ---------------------------------------------------
__device__ __forceinline__ uint32_t smem_u32(const void* p) {
    uint32_t a;
    asm("{ .reg .u64 t; cvta.to.shared.u64 t, %1; cvt.u32.u64 %0, t; }"
        : "=r"(a) : "l"(p));
    return a;
}
__device__ __forceinline__ void cp16(uint32_t s, const void* g) {
    asm volatile("cp.async.cg.shared.global [%0], [%1], 16;" :: "r"(s), "l"(g));
}
#define CP_COMMIT() asm volatile("cp.async.commit_group;")
#define CP_WAIT(n)  asm volatile("cp.async.wait_group %0;" :: "n"(n))

__device__ __forceinline__ void ldsm4(uint32_t* r, uint32_t a) {
    asm volatile("ldmatrix.sync.aligned.m8n8.x4.shared.b16 {%0,%1,%2,%3}, [%4];"
                 : "=r"(r[0]), "=r"(r[1]), "=r"(r[2]), "=r"(r[3]) : "r"(a));
}
__device__ __forceinline__ void mma_f16(float* c, const uint32_t* a,
                                        uint32_t b0, uint32_t b1) {
    asm volatile(
        "mma.sync.aligned.m16n8k16.row.col.f32.f16.f16.f32 "
        "{%0,%1,%2,%3}, {%4,%5,%6,%7}, {%8,%9}, {%0,%1,%2,%3};"
        : "+f"(c[0]), "+f"(c[1]), "+f"(c[2]), "+f"(c[3])
        : "r"(a[0]), "r"(a[1]), "r"(a[2]), "r"(a[3]), "r"(b0), "r"(b1));
}
__device__ __forceinline__ uint32_t pack2h(float a, float b) {
    __half2 t = __floats2half2_rn(a, b);
    return *reinterpret_cast<uint32_t*>(&t);
}
__device__ __forceinline__ float ex2f(float x) {
    float r;
    asm("ex2.approx.f32 %0, %1;" : "=f"(r) : "f"(x));
    return r;
}

// ---------------------------------------------------------------------------
// prep: fp32 -> fp16 convert (features); fused transpose for w1 AND w2
// ---------------------------------------------------------------------------
__global__ void cvt_k(const float* __restrict__ X, __half* __restrict__ Hi, size_t n)
{
    size_t stride = (size_t)gridDim.x * blockDim.x * 4;
    for (size_t i = ((size_t)blockIdx.x * blockDim.x + threadIdx.x) * 4; i < n; i += stride) {
        float4 v = *(const float4*)(X + i);
        __half h[4] = {__float2half_rn(v.x), __float2half_rn(v.y),
                       __float2half_rn(v.z), __float2half_rn(v.w)};
        *(uint2*)(Hi + i) = *(uint2*)h;
    }
}
__global__ void tprep_k(const float* __restrict__ W1, const float* __restrict__ W2,
                        __half* __restrict__ T1, __half* __restrict__ T2)
{
    __shared__ float t[32][33];
    const int bxr = blockIdx.x;
    const float* W;
    __half* T;
    int N, nxb;
    if (bxr < 64) { W = W1; T = T1; N = HH; nxb = bxr; }
    else          { W = W2; T = T2; N = FF; nxb = bxr - 64; }
    const int nx = nxb * 32, ky = blockIdx.y * 32;
    const int tx = threadIdx.x, ty = threadIdx.y;   // 32 x 8
#pragma unroll
    for (int i = 0; i < 4; i++)
        t[ty + 8 * i][tx] = W[(size_t)(ky + ty + 8 * i) * N + nx + tx];
    __syncthreads();
#pragma unroll
    for (int i = 0; i < 4; i++) {
        float v = t[tx][ty + 8 * i];
        T[(size_t)(nx + ty + 8 * i) * KK + ky + tx] = __float2half_rn(v);
    }
}

// ---------------------------------------------------------------------------
// GEMM1: pure fp16, 256x128 CTA tile, 512 threads (16 warps, 4x4), 1 CTA/SM.
// Kc=64, 3-stage x 48KB, one sync/iter, uniform tail commits.
// ---------------------------------------------------------------------------
__global__ __launch_bounds__(512, 1)
void hgemm1_k(const __half* __restrict__ Ahi, const __half* __restrict__ Bhi,
              const float* __restrict__ bias, int Nout, __half* __restrict__ Chi)
{
    extern __shared__ char smem[];
    const uint32_t sb = smem_u32(smem);
    const int tid = threadIdx.x;
    const int bx = blockIdx.x, by = blockIdx.y;
    const int lane = tid & 31, warp = tid >> 5;
    const int wm = warp & 3, wn = warp >> 2;        // 4 x 4 warp grid
    const int quad = lane >> 3, l8 = lane & 7;

    float* bias_s = (float*)(smem + 147456);
    if (tid < 128) bias_s[tid] = bias[bx * 128 + tid];

    const int arow = tid >> 1, ah4 = (tid & 1) * 4;
    const __half* gA0 = Ahi + (size_t)(by * 256 + arow) * KK;
    const uint32_t aslo = (uint32_t)(arow >> 3) * 1024 + (arow & 7) * 16;
    const int brow = tid >> 2, bh2 = (tid & 3) * 2;
    const __half* gB0 = Bhi + (size_t)(bx * 128 + brow) * KK;
    const uint32_t bslo = (uint32_t)(brow >> 3) * 1024 + (brow & 7) * 16;

    auto load_stage = [&](int kt) {
        uint32_t st = sb + (uint32_t)(kt % 3) * 49152;
        const int kbase = kt * 64;
#pragma unroll
        for (int j = 0; j < 4; j++) {
            int kb = ah4 + j;
            cp16(st + aslo + (uint32_t)kb * 128, gA0 + kbase + kb * 8);
        }
#pragma unroll
        for (int j = 0; j < 2; j++) {
            int kb = bh2 + j;
            cp16(st + 32768 + bslo + (uint32_t)kb * 128, gB0 + kbase + kb * 8);
        }
        CP_COMMIT();
    };

    float acc[4][4][4];
#pragma unroll
    for (int f = 0; f < 4; f++)
#pragma unroll
        for (int n = 0; n < 4; n++)
#pragma unroll
            for (int q = 0; q < 4; q++) acc[f][n][q] = 0.f;

    const uint32_t aoff = (uint32_t)(quad & 1) * 1024 + (uint32_t)(quad >> 1) * 128 + l8 * 16;
    const uint32_t boff = (uint32_t)(quad >> 1) * 1024 + (uint32_t)(quad & 1) * 128 + l8 * 16;

    const int NKT = KK / 64;   // 32
    load_stage(0);
    load_stage(1);
    for (int kt = 0; kt < NKT; kt++) {
        CP_WAIT(1);
        __syncthreads();
        if (kt + 2 < NKT) load_stage(kt + 2);
        else              CP_COMMIT();          // uniform accounting
        const uint32_t st = sb + (uint32_t)(kt % 3) * 49152;
#pragma unroll
        for (int ks = 0; ks < 4; ks++) {
            uint32_t ah[4][4], bh[2][4];
#pragma unroll
            for (int f = 0; f < 4; f++)
                ldsm4(ah[f], st + (uint32_t)(wm * 8 + f * 2) * 1024 + ks * 256 + aoff);
#pragma unroll
            for (int p = 0; p < 2; p++)
                ldsm4(bh[p], st + 32768 + (uint32_t)(wn * 4 + p * 2) * 1024 + ks * 256 + boff);
#pragma unroll
            for (int f = 0; f < 4; f++)
#pragma unroll
                for (int nf = 0; nf < 4; nf++) {
                    int p = nf >> 1, q = (nf & 1) * 2;
                    mma_f16(acc[f][nf], ah[f], bh[p][q], bh[p][q + 1]);
                }
        }
    }

    const int rsub = lane >> 2;
    const int csub = (lane & 3) * 2;
#pragma unroll
    for (int f = 0; f < 4; f++) {
        int r0 = by * 256 + wm * 64 + f * 16 + rsub;
#pragma unroll
        for (int nf = 0; nf < 4; nf++) {
            int cn = wn * 32 + nf * 8 + csub;
            float b0 = bias_s[cn], b1 = bias_s[cn + 1];
            float v00 = fmaxf(acc[f][nf][0] + b0, 0.f);
            float v01 = fmaxf(acc[f][nf][1] + b1, 0.f);
            float v10 = fmaxf(acc[f][nf][2] + b0, 0.f);
            float v11 = fmaxf(acc[f][nf][3] + b1, 0.f);
            size_t o0 = (size_t)r0 * Nout + bx * 128 + cn;
            size_t o1 = o0 + (size_t)8 * Nout;
            *(uint32_t*)(Chi + o0) = pack2h(v00, v01);
            *(uint32_t*)(Chi + o1) = pack2h(v10, v11);
        }
    }
}

// ---------------------------------------------------------------------------
// GEMM2 v2: split-K=4, 256-row tiles, 512 threads (4x4 warps), 1 CTA/SM.
// Writes raw fp32 partials (no bias) to P4[ks][row][col].
// B cp.async op count cut 4x vs the 64-row version (issue-bound fix).
// Kc=32, 4-stage x 24KB, uniform tail commits.
// ---------------------------------------------------------------------------
__global__ __launch_bounds__(512, 1)
void hgemm2_k(const __half* __restrict__ Ahi, const __half* __restrict__ Bhi,
              float* __restrict__ P4)
{
    extern __shared__ char smem[];
    const uint32_t sb = smem_u32(smem);
    const int tid = threadIdx.x;
    const int ks4 = blockIdx.x, by = blockIdx.y;
    const int lane = tid & 31, warp = tid >> 5;
    const int wm = warp & 3, wn = warp >> 2;
    const int quad = lane >> 3, l8 = lane & 7;

    // A loader: 256 rows, 2 threads/row, 2 cp16 each
    const int arow = tid >> 1, a2 = (tid & 1) * 2;
    const __half* gA0 = Ahi + (size_t)(by * 256 + arow) * KK + ks4 * 512;
    const uint32_t aslo = (uint32_t)(arow >> 3) * 512 + (arow & 7) * 16;
    // B loader: 128 rows, 4 threads/row, 1 cp16 each
    const int brow = tid >> 2, bkb = tid & 3;
    const __half* gB0 = Bhi + (size_t)brow * KK + ks4 * 512;
    const uint32_t bslo = (uint32_t)(brow >> 3) * 512 + (brow & 7) * 16;

    auto load_stage = [&](int kt) {
        uint32_t st = sb + (uint32_t)(kt & 3) * 24576;
        const int kbase = kt * 32;
#pragma unroll
        for (int j = 0; j < 2; j++) {
            int kb = a2 + j;
            cp16(st + aslo + (uint32_t)kb * 128, gA0 + kbase + kb * 8);
        }
        cp16(st + 16384 + bslo + (uint32_t)bkb * 128, gB0 + kbase + bkb * 8);
        CP_COMMIT();
    };

    float acc[4][4][4];
#pragma unroll
    for (int f = 0; f < 4; f++)
#pragma unroll
        for (int n = 0; n < 4; n++)
#pragma unroll
            for (int q = 0; q < 4; q++) acc[f][n][q] = 0.f;

    const uint32_t aoff = (uint32_t)(quad & 1) * 512 + (uint32_t)(quad >> 1) * 128 + l8 * 16;
    const uint32_t boff = (uint32_t)(quad >> 1) * 512 + (uint32_t)(quad & 1) * 128 + l8 * 16;

    const int NKT = 512 / 32;   // 16
    load_stage(0); load_stage(1); load_stage(2);
    for (int kt = 0; kt < NKT; kt++) {
        CP_WAIT(2);
        __syncthreads();
        if (kt + 3 < NKT) load_stage(kt + 3);
        else              CP_COMMIT();          // uniform accounting
        const uint32_t st = sb + (uint32_t)(kt & 3) * 24576;
#pragma unroll
        for (int ks = 0; ks < 2; ks++) {
            uint32_t ah[4][4], bh[2][4];
#pragma unroll
            for (int f = 0; f < 4; f++)
                ldsm4(ah[f], st + (uint32_t)(wm * 8 + f * 2) * 512 + ks * 256 + aoff);
#pragma unroll
            for (int p = 0; p < 2; p++)
                ldsm4(bh[p], st + 16384 + (uint32_t)(wn * 4 + p * 2) * 512 + ks * 256 + boff);
#pragma unroll
            for (int f = 0; f < 4; f++)
#pragma unroll
                for (int nf = 0; nf < 4; nf++) {
                    int p = nf >> 1, q = (nf & 1) * 2;
                    mma_f16(acc[f][nf], ah[f], bh[p][q], bh[p][q + 1]);
                }
        }
    }

    const int rsub = lane >> 2;
    const int csub = (lane & 3) * 2;
#pragma unroll
    for (int f = 0; f < 4; f++) {
        int r0 = by * 256 + wm * 64 + f * 16 + rsub;
#pragma unroll
        for (int nf = 0; nf < 4; nf++) {
            int cn = wn * 32 + nf * 8 + csub;
            size_t o0 = ((size_t)ks4 * MB + r0) * FF + cn;
            size_t o1 = o0 + (size_t)8 * FF;
            *(float2*)(P4 + o0) = make_float2(acc[f][nf][0], acc[f][nf][1]);
            *(float2*)(P4 + o1) = make_float2(acc[f][nf][2], acc[f][nf][3]);
        }
    }
}

// ---------------------------------------------------------------------------
// combine: p = sum of 4 partials + bias; L2-normalize; emit z, zhi, outz.
// One 128-thread block per row. Fixed summation order -> deterministic.
// ---------------------------------------------------------------------------
__global__ void combine_k(const float* __restrict__ P4, const float* __restrict__ bias,
                          float* __restrict__ Zf, __half* __restrict__ Zhi,
                          float* __restrict__ outz)
{
    const int row = blockIdx.x;
    const int t = threadIdx.x;
    const size_t o = (size_t)row * FF + t;
    float v = P4[o] + P4[(size_t)MB * FF + o] + P4[(size_t)2 * MB * FF + o]
            + P4[(size_t)3 * MB * FF + o] + bias[t];
    float s = v * v;
#pragma unroll
    for (int off = 16; off; off >>= 1) s += __shfl_xor_sync(0xffffffffu, s, off);
    __shared__ float ws[4];
    if ((t & 31) == 0) ws[t >> 5] = s;
    __syncthreads();
    float inv = rsqrtf(fmaxf(ws[0] + ws[1] + ws[2] + ws[3], 1e-24f));
    float z = v * inv;
    Zf[o] = z;
    Zhi[o] = __float2half_rn(z);
    if (outz) outz[o] = z;
}

// ---------------------------------------------------------------------------
// Triangular lse tile kernel (lower triangle, 8256 CTAs).
// ---------------------------------------------------------------------------
__global__ __launch_bounds__(256, 2)
void lse_tri_k(const __half* __restrict__ Zhi, float* __restrict__ ps)
{
    extern __shared__ char smem[];
    const uint32_t sb = smem_u32(smem);
    float* colarr = (float*)(smem + 65536);   // [2][128]
    float* lsum4  = (float*)(smem + 66560);   // [4][128]

    const int tid = threadIdx.x;
    const int lane = tid & 31, warp = tid >> 5;
    const int wm = warp & 1, wn = warp >> 1;
    const int quad = lane >> 3, l8 = lane & 7;

    const int t = blockIdx.x;
    int by = (int)((sqrtf(8.0f * (float)t + 1.0f) - 1.0f) * 0.5f);
    while ((by + 1) * (by + 2) / 2 <= t) by++;
    while (by * (by + 1) / 2 > t) by--;
    const int bx = t - by * (by + 1) / 2;

    const int lrow = tid >> 1, lhalf = tid & 1;
    const uint32_t lso = (uint32_t)(lrow >> 3) * 2048 + (lrow & 7) * 16;
    {
        const __half* ga = Zhi + (size_t)(by * 128 + lrow) * FF;
        const __half* gb = Zhi + (size_t)(bx * 128 + lrow) * FF;
#pragma unroll
        for (int j = 0; j < 8; j++) {
            int kb = lhalf * 8 + j;
            cp16(sb + lso + kb * 128,         ga + kb * 8);
            cp16(sb + 32768 + lso + kb * 128, gb + kb * 8);
        }
        CP_COMMIT();
    }
    CP_WAIT(0);
    __syncthreads();

    float acc[4][4][4];
#pragma unroll
    for (int f = 0; f < 4; f++)
#pragma unroll
        for (int n = 0; n < 4; n++)
#pragma unroll
            for (int q = 0; q < 4; q++) acc[f][n][q] = 0.f;

    const uint32_t aoff = (uint32_t)(quad & 1) * 2048 + (uint32_t)(quad >> 1) * 128 + l8 * 16;
    const uint32_t boff = (uint32_t)(quad >> 1) * 2048 + (uint32_t)(quad & 1) * 128 + l8 * 16;

#pragma unroll
    for (int ks = 0; ks < 8; ks++) {
        uint32_t ah[4][4], bh[2][4];
#pragma unroll
        for (int f = 0; f < 4; f++)
            ldsm4(ah[f], sb + (uint32_t)(wm * 8 + f * 2) * 2048 + ks * 256 + aoff);
#pragma unroll
        for (int p = 0; p < 2; p++)
            ldsm4(bh[p], sb + 32768 + (uint32_t)(wn * 4 + p * 2) * 2048 + ks * 256 + boff);
#pragma unroll
        for (int f = 0; f < 4; f++)
#pragma unroll
            for (int nf = 0; nf < 4; nf++) {
                int p = nf >> 1, q = (nf & 1) * 2;
                mma_f16(acc[f][nf], ah[f], bh[p][q], bh[p][q + 1]);
            }
    }

    const int rsub = lane >> 2;
    const int csub = (lane & 3) * 2;
    const bool diag = (by == bx);

    float rs[4][2];
    float colp[4][2];
#pragma unroll
    for (int f = 0; f < 4; f++) { rs[f][0] = 0.f; rs[f][1] = 0.f; }
#pragma unroll
    for (int nf = 0; nf < 4; nf++) { colp[nf][0] = 0.f; colp[nf][1] = 0.f; }

#pragma unroll
    for (int f = 0; f < 4; f++) {
#pragma unroll
        for (int nf = 0; nf < 4; nf++) {
            float e00 = ex2f(fmaf(acc[f][nf][0], C_EX2, -C_EX2));
            float e01 = ex2f(fmaf(acc[f][nf][1], C_EX2, -C_EX2));
            float e10 = ex2f(fmaf(acc[f][nf][2], C_EX2, -C_EX2));
            float e11 = ex2f(fmaf(acc[f][nf][3], C_EX2, -C_EX2));
            if (diag) {
                int lr = wm * 64 + f * 16 + rsub;
                int lc = wn * 32 + nf * 8 + csub;
                if (lr == lc)         e00 = 0.f;
                if (lr == lc + 1)     e01 = 0.f;
                if (lr + 8 == lc)     e10 = 0.f;
                if (lr + 8 == lc + 1) e11 = 0.f;
            }
            rs[f][0] += e00 + e01;
            rs[f][1] += e10 + e11;
            colp[nf][0] += e00 + e10;
            colp[nf][1] += e01 + e11;
        }
    }

#pragma unroll
    for (int f = 0; f < 4; f++) {
#pragma unroll
        for (int h = 0; h < 2; h++) {
            float v = rs[f][h];
            v += __shfl_xor_sync(0xffffffffu, v, 1);
            v += __shfl_xor_sync(0xffffffffu, v, 2);
            if ((lane & 3) == 0)
                lsum4[wn * 128 + wm * 64 + f * 16 + h * 8 + rsub] = v;
        }
    }
#pragma unroll
    for (int nf = 0; nf < 4; nf++) {
#pragma unroll
        for (int h = 0; h < 2; h++) {
            float v = colp[nf][h];
            v += __shfl_xor_sync(0xffffffffu, v, 4);
            v += __shfl_xor_sync(0xffffffffu, v, 8);
            v += __shfl_xor_sync(0xffffffffu, v, 16);
            if (lane < 4)
                colarr[wm * 128 + wn * 32 + nf * 8 + lane * 2 + h] = v;
        }
    }
    __syncthreads();
    if (tid < 128) {
        float rtot = lsum4[tid] + lsum4[128 + tid] + lsum4[256 + tid] + lsum4[384 + tid];
        ps[(size_t)bx * MB + by * 128 + tid] = rtot;
        if (!diag) {
            float ctot = colarr[tid] + colarr[128 + tid];
            ps[(size_t)by * MB + bx * 128 + tid] = ctot;
        }
    }
}

// ---------------------------------------------------------------------------
__global__ void sumps_k(const float* __restrict__ ps, float* __restrict__ lse)
{
    const int row = blockIdx.x * 256 + threadIdx.x;
    float tot = 0.f;
#pragma unroll 8
    for (int c = 0; c < 128; c++) tot += ps[(size_t)c * MB + row];
    lse[row] = logf(tot) + INV_T;
}

__global__ void pos_k(const float* __restrict__ Z, float* __restrict__ pos)
{
    const int row = blockIdx.x;
    const int t = threadIdx.x;
    const int prow = (row + MB / 2) & (MB - 1);
    float s = Z[(size_t)row * FF + t] * Z[(size_t)prow * FF + t];
#pragma unroll
    for (int o = 16; o; o >>= 1) s += __shfl_xor_sync(0xffffffffu, s, o);
    __shared__ float ws[4];
    if ((t & 31) == 0) ws[t >> 5] = s;
    __syncthreads();
    if (t == 0) pos[row] = (ws[0] + ws[1] + ws[2] + ws[3]) * INV_T;
}

__global__ void loss_k(const float* __restrict__ lse, const float* __restrict__ pos,
                       float* __restrict__ out)
{
    __shared__ float sm[256];
    const int t = threadIdx.x;
    float s = 0.f;
    for (int i = t; i < MB; i += 256) s += lse[i] - pos[i];
    sm[t] = s;
    __syncthreads();
    for (int o = 128; o; o >>= 1) {
        if (t < o) sm[t] += sm[t + o];
        __syncthreads();
    }
    if (t == 0) out[0] = sm[0] * (1.0f / MB);
}

// ---------------------------------------------------------------------------
extern "C" void kernel_launch(void* const* d_in, const int* in_sizes, int n_in,
                              void* d_out, int out_size)
{
    const float* features = (const float*)d_in[0];
    const float* w1 = (const float*)d_in[1];
    const float* b1 = (const float*)d_in[2];
    const float* w2 = (const float*)d_in[3];
    const float* b2 = (const float*)d_in[4];
    float* out = (float*)d_out;

    __half *fhi, *w1hi, *w2hi, *hhi, *zhi;
    float *z, *p4b, *psb, *lseb, *posb;
    cudaGetSymbolAddress((void**)&fhi,  g_fhi);
    cudaGetSymbolAddress((void**)&w1hi, g_w1hi);
    cudaGetSymbolAddress((void**)&w2hi, g_w2hi);
    cudaGetSymbolAddress((void**)&hhi,  g_hhi);
    cudaGetSymbolAddress((void**)&zhi,  g_zhi);
    cudaGetSymbolAddress((void**)&z,    g_z);
    cudaGetSymbolAddress((void**)&p4b,  g_p4);
    cudaGetSymbolAddress((void**)&psb,  g_ps);
    cudaGetSymbolAddress((void**)&lseb, g_lse);
    cudaGetSymbolAddress((void**)&posb, g_pos);

    const int SM_G1 = 147456 + 512;          // 3 stages x 48KB + bias
    const int SM_G2 = 98304;                 // 4 stages x 24KB
    const int SM_L  = 65536 + 1024 + 2048;   // A + B + colarr + lsum
    cudaFuncSetAttribute(hgemm1_k, cudaFuncAttributeMaxDynamicSharedMemorySize, SM_G1);
    cudaFuncSetAttribute(hgemm2_k, cudaFuncAttributeMaxDynamicSharedMemorySize, SM_G2);
    cudaFuncSetAttribute(lse_tri_k, cudaFuncAttributeMaxDynamicSharedMemorySize, SM_L);

    // prep
    cvt_k<<<2048, 256>>>(features, fhi, (size_t)MB * DD);
    tprep_k<<<dim3(64 + FF / 32, KK / 32), dim3(32, 8)>>>(w1, w2, w1hi, w2hi);

    // 1) h = relu(features @ w1 + b1)
    hgemm1_k<<<dim3(HH / 128, MB / 256), 512, SM_G1>>>(fhi, w1hi, b1, HH, hhi);

    // 2) p partials (split-K=4, 256-row tiles), then combine+normalize
    hgemm2_k<<<dim3(4, MB / 256), 512, SM_G2>>>(hhi, w2hi, p4b);
    float* outz = (out_size >= 1 + MB * FF) ? (out + 1) : nullptr;
    combine_k<<<MB, 128>>>(p4b, b2, z, zhi, outz);

    // 3) pos
    pos_k<<<MB, 128>>>(z, posb);

    // 4) triangular masked exp-sum tiles
    const int NTRI = (MB / 128) * (MB / 128 + 1) / 2;   // 8256
    lse_tri_k<<<NTRI, 256, SM_L>>>(zhi, psb);

    // 5) combine partials -> lse, 6) loss
    sumps_k<<<MB / 256, 256>>>(psb, lseb);
    loss_k<<<1, 256>>>(lseb, posb, out);
}

// round 17
// speedup vs baseline: 1.0727x; 1.0308x over previous
#include <cuda_runtime.h>
#include <cuda_fp16.h>
#include <math.h>
#include <stdint.h>

#define MB 16384   // rows (2N)
#define DD 2048
#define HH 2048
#define FF 128
#define KK 2048    // K of both big GEMMs
#define SEG 16     // lse strip segment length (tiles)

constexpr float INV_T = 1.0f / 0.07f;
constexpr float C_EX2 = 20.6099773964f;   // INV_T * log2(e)

// ---------------- scratch --------------------------------------------------
__device__ __half g_fhi [(size_t)MB * DD];
__device__ __half g_w1hi[(size_t)HH * DD];
__device__ __half g_w2hi[(size_t)FF * HH];
__device__ __half g_hhi [(size_t)MB * HH];
__device__ __half g_zhi [(size_t)MB * FF];
__device__ float g_z  [(size_t)MB * FF];
__device__ float g_p4 [(size_t)4 * MB * FF];   // 32MB split-K partials
__device__ float g_ps [(size_t)128 * MB];      // 8MB partial exp-sums
__device__ float g_lse[MB];
__device__ float g_pos[MB];

// ---------------- helpers ---------------------------------------------------
__device__ __forceinline__ uint32_t smem_u32(const void* p) {
    uint32_t a;
    asm("{ .reg .u64 t; cvta.to.shared.u64 t, %1; cvt.u32.u64 %0, t; }"
        : "=r"(a) : "l"(p));
    return a;
}
__device__ __forceinline__ void cp16(uint32_t s, const void* g) {
    asm volatile("cp.async.cg.shared.global [%0], [%1], 16;" :: "r"(s), "l"(g));
}
#define CP_COMMIT() asm volatile("cp.async.commit_group;")
#define CP_WAIT(n)  asm volatile("cp.async.wait_group %0;" :: "n"(n))

__device__ __forceinline__ void ldsm4(uint32_t* r, uint32_t a) {
    asm volatile("ldmatrix.sync.aligned.m8n8.x4.shared.b16 {%0,%1,%2,%3}, [%4];"
                 : "=r"(r[0]), "=r"(r[1]), "=r"(r[2]), "=r"(r[3]) : "r"(a));
}
__device__ __forceinline__ void mma_f16(float* c, const uint32_t* a,
                                        uint32_t b0, uint32_t b1) {
    asm volatile(
        "mma.sync.aligned.m16n8k16.row.col.f32.f16.f16.f32 "
        "{%0,%1,%2,%3}, {%4,%5,%6,%7}, {%8,%9}, {%0,%1,%2,%3};"
        : "+f"(c[0]), "+f"(c[1]), "+f"(c[2]), "+f"(c[3])
        : "r"(a[0]), "r"(a[1]), "r"(a[2]), "r"(a[3]), "r"(b0), "r"(b1));
}
__device__ __forceinline__ uint32_t pack2h(float a, float b) {
    __half2 t = __floats2half2_rn(a, b);
    return *reinterpret_cast<uint32_t*>(&t);
}
__device__ __forceinline__ float ex2f(float x) {
    float r;
    asm("ex2.approx.f32 %0, %1;" : "=f"(r) : "f"(x));
    return r;
}

// ---------------------------------------------------------------------------
// prep
// ---------------------------------------------------------------------------
__global__ void cvt_k(const float* __restrict__ X, __half* __restrict__ Hi, size_t n)
{
    size_t stride = (size_t)gridDim.x * blockDim.x * 4;
    for (size_t i = ((size_t)blockIdx.x * blockDim.x + threadIdx.x) * 4; i < n; i += stride) {
        float4 v = *(const float4*)(X + i);
        __half h[4] = {__float2half_rn(v.x), __float2half_rn(v.y),
                       __float2half_rn(v.z), __float2half_rn(v.w)};
        *(uint2*)(Hi + i) = *(uint2*)h;
    }
}
__global__ void tprep_k(const float* __restrict__ W1, const float* __restrict__ W2,
                        __half* __restrict__ T1, __half* __restrict__ T2)
{
    __shared__ float t[32][33];
    const int bxr = blockIdx.x;
    const float* W;
    __half* T;
    int N, nxb;
    if (bxr < 64) { W = W1; T = T1; N = HH; nxb = bxr; }
    else          { W = W2; T = T2; N = FF; nxb = bxr - 64; }
    const int nx = nxb * 32, ky = blockIdx.y * 32;
    const int tx = threadIdx.x, ty = threadIdx.y;
#pragma unroll
    for (int i = 0; i < 4; i++)
        t[ty + 8 * i][tx] = W[(size_t)(ky + ty + 8 * i) * N + nx + tx];
    __syncthreads();
#pragma unroll
    for (int i = 0; i < 4; i++) {
        float v = t[tx][ty + 8 * i];
        T[(size_t)(nx + ty + 8 * i) * KK + ky + tx] = __float2half_rn(v);
    }
}

// ---------------------------------------------------------------------------
// GEMM1: pure fp16, 256x128 CTA tile, 512 threads, Kc=64, 3-stage.
// ---------------------------------------------------------------------------
__global__ __launch_bounds__(512, 1)
void hgemm1_k(const __half* __restrict__ Ahi, const __half* __restrict__ Bhi,
              const float* __restrict__ bias, int Nout, __half* __restrict__ Chi)
{
    extern __shared__ char smem[];
    const uint32_t sb = smem_u32(smem);
    const int tid = threadIdx.x;
    const int bx = blockIdx.x, by = blockIdx.y;
    const int lane = tid & 31, warp = tid >> 5;
    const int wm = warp & 3, wn = warp >> 2;
    const int quad = lane >> 3, l8 = lane & 7;

    float* bias_s = (float*)(smem + 147456);
    if (tid < 128) bias_s[tid] = bias[bx * 128 + tid];

    const int arow = tid >> 1, ah4 = (tid & 1) * 4;
    const __half* gA0 = Ahi + (size_t)(by * 256 + arow) * KK;
    const uint32_t aslo = (uint32_t)(arow >> 3) * 1024 + (arow & 7) * 16;
    const int brow = tid >> 2, bh2 = (tid & 3) * 2;
    const __half* gB0 = Bhi + (size_t)(bx * 128 + brow) * KK;
    const uint32_t bslo = (uint32_t)(brow >> 3) * 1024 + (brow & 7) * 16;

    auto load_stage = [&](int kt) {
        uint32_t st = sb + (uint32_t)(kt % 3) * 49152;
        const int kbase = kt * 64;
#pragma unroll
        for (int j = 0; j < 4; j++) {
            int kb = ah4 + j;
            cp16(st + aslo + (uint32_t)kb * 128, gA0 + kbase + kb * 8);
        }
#pragma unroll
        for (int j = 0; j < 2; j++) {
            int kb = bh2 + j;
            cp16(st + 32768 + bslo + (uint32_t)kb * 128, gB0 + kbase + kb * 8);
        }
        CP_COMMIT();
    };

    float acc[4][4][4];
#pragma unroll
    for (int f = 0; f < 4; f++)
#pragma unroll
        for (int n = 0; n < 4; n++)
#pragma unroll
            for (int q = 0; q < 4; q++) acc[f][n][q] = 0.f;

    const uint32_t aoff = (uint32_t)(quad & 1) * 1024 + (uint32_t)(quad >> 1) * 128 + l8 * 16;
    const uint32_t boff = (uint32_t)(quad >> 1) * 1024 + (uint32_t)(quad & 1) * 128 + l8 * 16;

    const int NKT = KK / 64;
    load_stage(0);
    load_stage(1);
    for (int kt = 0; kt < NKT; kt++) {
        CP_WAIT(1);
        __syncthreads();
        if (kt + 2 < NKT) load_stage(kt + 2);
        else              CP_COMMIT();
        const uint32_t st = sb + (uint32_t)(kt % 3) * 49152;
#pragma unroll
        for (int ks = 0; ks < 4; ks++) {
            uint32_t ah[4][4], bh[2][4];
#pragma unroll
            for (int f = 0; f < 4; f++)
                ldsm4(ah[f], st + (uint32_t)(wm * 8 + f * 2) * 1024 + ks * 256 + aoff);
#pragma unroll
            for (int p = 0; p < 2; p++)
                ldsm4(bh[p], st + 32768 + (uint32_t)(wn * 4 + p * 2) * 1024 + ks * 256 + boff);
#pragma unroll
            for (int f = 0; f < 4; f++)
#pragma unroll
                for (int nf = 0; nf < 4; nf++) {
                    int p = nf >> 1, q = (nf & 1) * 2;
                    mma_f16(acc[f][nf], ah[f], bh[p][q], bh[p][q + 1]);
                }
        }
    }

    const int rsub = lane >> 2;
    const int csub = (lane & 3) * 2;
#pragma unroll
    for (int f = 0; f < 4; f++) {
        int r0 = by * 256 + wm * 64 + f * 16 + rsub;
#pragma unroll
        for (int nf = 0; nf < 4; nf++) {
            int cn = wn * 32 + nf * 8 + csub;
            float b0 = bias_s[cn], b1 = bias_s[cn + 1];
            float v00 = fmaxf(acc[f][nf][0] + b0, 0.f);
            float v01 = fmaxf(acc[f][nf][1] + b1, 0.f);
            float v10 = fmaxf(acc[f][nf][2] + b0, 0.f);
            float v11 = fmaxf(acc[f][nf][3] + b1, 0.f);
            size_t o0 = (size_t)r0 * Nout + bx * 128 + cn;
            size_t o1 = o0 + (size_t)8 * Nout;
            *(uint32_t*)(Chi + o0) = pack2h(v00, v01);
            *(uint32_t*)(Chi + o1) = pack2h(v10, v11);
        }
    }
}

// ---------------------------------------------------------------------------
// GEMM2: split-K=4, 256-row tiles, 512 threads, raw partials to P4.
// ---------------------------------------------------------------------------
__global__ __launch_bounds__(512, 1)
void hgemm2_k(const __half* __restrict__ Ahi, const __half* __restrict__ Bhi,
              float* __restrict__ P4)
{
    extern __shared__ char smem[];
    const uint32_t sb = smem_u32(smem);
    const int tid = threadIdx.x;
    const int ks4 = blockIdx.x, by = blockIdx.y;
    const int lane = tid & 31, warp = tid >> 5;
    const int wm = warp & 3, wn = warp >> 2;
    const int quad = lane >> 3, l8 = lane & 7;

    const int arow = tid >> 1, a2 = (tid & 1) * 2;
    const __half* gA0 = Ahi + (size_t)(by * 256 + arow) * KK + ks4 * 512;
    const uint32_t aslo = (uint32_t)(arow >> 3) * 512 + (arow & 7) * 16;
    const int brow = tid >> 2, bkb = tid & 3;
    const __half* gB0 = Bhi + (size_t)brow * KK + ks4 * 512;
    const uint32_t bslo = (uint32_t)(brow >> 3) * 512 + (brow & 7) * 16;

    auto load_stage = [&](int kt) {
        uint32_t st = sb + (uint32_t)(kt & 3) * 24576;
        const int kbase = kt * 32;
#pragma unroll
        for (int j = 0; j < 2; j++) {
            int kb = a2 + j;
            cp16(st + aslo + (uint32_t)kb * 128, gA0 + kbase + kb * 8);
        }
        cp16(st + 16384 + bslo + (uint32_t)bkb * 128, gB0 + kbase + bkb * 8);
        CP_COMMIT();
    };

    float acc[4][4][4];
#pragma unroll
    for (int f = 0; f < 4; f++)
#pragma unroll
        for (int n = 0; n < 4; n++)
#pragma unroll
            for (int q = 0; q < 4; q++) acc[f][n][q] = 0.f;

    const uint32_t aoff = (uint32_t)(quad & 1) * 512 + (uint32_t)(quad >> 1) * 128 + l8 * 16;
    const uint32_t boff = (uint32_t)(quad >> 1) * 512 + (uint32_t)(quad & 1) * 128 + l8 * 16;

    const int NKT = 512 / 32;
    load_stage(0); load_stage(1); load_stage(2);
    for (int kt = 0; kt < NKT; kt++) {
        CP_WAIT(2);
        __syncthreads();
        if (kt + 3 < NKT) load_stage(kt + 3);
        else              CP_COMMIT();
        const uint32_t st = sb + (uint32_t)(kt & 3) * 24576;
#pragma unroll
        for (int ks = 0; ks < 2; ks++) {
            uint32_t ah[4][4], bh[2][4];
#pragma unroll
            for (int f = 0; f < 4; f++)
                ldsm4(ah[f], st + (uint32_t)(wm * 8 + f * 2) * 512 + ks * 256 + aoff);
#pragma unroll
            for (int p = 0; p < 2; p++)
                ldsm4(bh[p], st + 16384 + (uint32_t)(wn * 4 + p * 2) * 512 + ks * 256 + boff);
#pragma unroll
            for (int f = 0; f < 4; f++)
#pragma unroll
                for (int nf = 0; nf < 4; nf++) {
                    int p = nf >> 1, q = (nf & 1) * 2;
                    mma_f16(acc[f][nf], ah[f], bh[p][q], bh[p][q + 1]);
                }
        }
    }

    const int rsub = lane >> 2;
    const int csub = (lane & 3) * 2;
#pragma unroll
    for (int f = 0; f < 4; f++) {
        int r0 = by * 256 + wm * 64 + f * 16 + rsub;
#pragma unroll
        for (int nf = 0; nf < 4; nf++) {
            int cn = wn * 32 + nf * 8 + csub;
            size_t o0 = ((size_t)ks4 * MB + r0) * FF + cn;
            size_t o1 = o0 + (size_t)8 * FF;
            *(float2*)(P4 + o0) = make_float2(acc[f][nf][0], acc[f][nf][1]);
            *(float2*)(P4 + o1) = make_float2(acc[f][nf][2], acc[f][nf][3]);
        }
    }
}

// ---------------------------------------------------------------------------
// combine: p = sum of 4 partials + bias; L2-normalize; emit z, zhi, outz.
// ---------------------------------------------------------------------------
__global__ void combine_k(const float* __restrict__ P4, const float* __restrict__ bias,
                          float* __restrict__ Zf, __half* __restrict__ Zhi,
                          float* __restrict__ outz)
{
    const int row = blockIdx.x;
    const int t = threadIdx.x;
    const size_t o = (size_t)row * FF + t;
    float v = P4[o] + P4[(size_t)MB * FF + o] + P4[(size_t)2 * MB * FF + o]
            + P4[(size_t)3 * MB * FF + o] + bias[t];
    float s = v * v;
#pragma unroll
    for (int off = 16; off; off >>= 1) s += __shfl_xor_sync(0xffffffffu, s, off);
    __shared__ float ws[4];
    if ((t & 31) == 0) ws[t >> 5] = s;
    __syncthreads();
    float inv = rsqrtf(fmaxf(ws[0] + ws[1] + ws[2] + ws[3], 1e-24f));
    float z = v * inv;
    Zf[o] = z;
    Zhi[o] = __float2half_rn(z);
    if (outz) outz[o] = z;
}

// ---------------------------------------------------------------------------
// lse strips: CTA = (by, 16-tile bx segment of the lower triangle).
// A (by rows) loaded ONCE; B double-buffered so loads overlap MMA+exp.
// Row-sums accumulate in regs across the segment -> ps[bx0][by rows]
// (+ zeros for the other segment slots); col-sums per tile -> ps[by][bx rows].
// Every ps slot written exactly once -> deterministic; sumps unchanged.
// smem: A 32K | B0 32K | B1 32K | colarr 1K | lsum 2K. 2 CTAs/SM.
// ---------------------------------------------------------------------------
__global__ __launch_bounds__(256, 2)
void lse_strip_k(const __half* __restrict__ Zhi, float* __restrict__ ps)
{
    const int by = blockIdx.y;
    const int bx0 = blockIdx.x * SEG;
    if (bx0 > by) return;
    const int bx1 = min(bx0 + SEG - 1, by);

    extern __shared__ char smem[];
    const uint32_t sb = smem_u32(smem);
    float* colarr = (float*)(smem + 98304);   // [2][128]
    float* lsum4  = (float*)(smem + 99328);   // [4][128]

    const int tid = threadIdx.x;
    const int lane = tid & 31, warp = tid >> 5;
    const int wm = warp & 1, wn = warp >> 1;
    const int quad = lane >> 3, l8 = lane & 7;

    const int lrow = tid >> 1, lhalf = tid & 1;
    const uint32_t lso = (uint32_t)(lrow >> 3) * 2048 + (lrow & 7) * 16;

    auto loadB = [&](int bx, int s) {
        uint32_t st = sb + 32768 + (uint32_t)s * 32768;
        const __half* gb = Zhi + (size_t)(bx * 128 + lrow) * FF;
#pragma unroll
        for (int j = 0; j < 8; j++) {
            int kb = lhalf * 8 + j;
            cp16(st + lso + kb * 128, gb + kb * 8);
        }
        CP_COMMIT();
    };

    // A (rows of by) + first B, single commit group via loadB's commit
    {
        const __half* ga = Zhi + (size_t)(by * 128 + lrow) * FF;
#pragma unroll
        for (int j = 0; j < 8; j++) {
            int kb = lhalf * 8 + j;
            cp16(sb + lso + kb * 128, ga + kb * 8);
        }
        loadB(bx0, 0);
    }

    const uint32_t aoff = (uint32_t)(quad & 1) * 2048 + (uint32_t)(quad >> 1) * 128 + l8 * 16;
    const uint32_t boff = (uint32_t)(quad >> 1) * 2048 + (uint32_t)(quad & 1) * 128 + l8 * 16;
    const int rsub = lane >> 2;
    const int csub = (lane & 3) * 2;

    float rs[4][2];
#pragma unroll
    for (int f = 0; f < 4; f++) { rs[f][0] = 0.f; rs[f][1] = 0.f; }

    for (int bx = bx0; bx <= bx1; bx++) {
        const int s = (bx - bx0) & 1;
        CP_WAIT(0);
        __syncthreads();            // B(s) ready; also protects colarr reuse
        if (bx < bx1) loadB(bx + 1, s ^ 1);   // overlaps MMA + epilogue below

        float acc[4][4][4];
#pragma unroll
        for (int f = 0; f < 4; f++)
#pragma unroll
            for (int n = 0; n < 4; n++)
#pragma unroll
                for (int q = 0; q < 4; q++) acc[f][n][q] = 0.f;

        const uint32_t stB = sb + 32768 + (uint32_t)s * 32768;
#pragma unroll
        for (int ks = 0; ks < 8; ks++) {
            uint32_t ah[4][4], bh[2][4];
#pragma unroll
            for (int f = 0; f < 4; f++)
                ldsm4(ah[f], sb + (uint32_t)(wm * 8 + f * 2) * 2048 + ks * 256 + aoff);
#pragma unroll
            for (int p = 0; p < 2; p++)
                ldsm4(bh[p], stB + (uint32_t)(wn * 4 + p * 2) * 2048 + ks * 256 + boff);
#pragma unroll
            for (int f = 0; f < 4; f++)
#pragma unroll
                for (int nf = 0; nf < 4; nf++) {
                    int p = nf >> 1, q = (nf & 1) * 2;
                    mma_f16(acc[f][nf], ah[f], bh[p][q], bh[p][q + 1]);
                }
        }

        const bool diag = (bx == by);
        float colp[4][2];
#pragma unroll
        for (int nf = 0; nf < 4; nf++) { colp[nf][0] = 0.f; colp[nf][1] = 0.f; }

#pragma unroll
        for (int f = 0; f < 4; f++) {
#pragma unroll
            for (int nf = 0; nf < 4; nf++) {
                float e00 = ex2f(fmaf(acc[f][nf][0], C_EX2, -C_EX2));
                float e01 = ex2f(fmaf(acc[f][nf][1], C_EX2, -C_EX2));
                float e10 = ex2f(fmaf(acc[f][nf][2], C_EX2, -C_EX2));
                float e11 = ex2f(fmaf(acc[f][nf][3], C_EX2, -C_EX2));
                if (diag) {
                    int lr = wm * 64 + f * 16 + rsub;
                    int lc = wn * 32 + nf * 8 + csub;
                    if (lr == lc)         e00 = 0.f;
                    if (lr == lc + 1)     e01 = 0.f;
                    if (lr + 8 == lc)     e10 = 0.f;
                    if (lr + 8 == lc + 1) e11 = 0.f;
                }
                rs[f][0] += e00 + e01;
                rs[f][1] += e10 + e11;
                colp[nf][0] += e00 + e10;
                colp[nf][1] += e01 + e11;
            }
        }

        // per-tile column-sum reduction and write (skipped on diag)
        if (!diag) {
#pragma unroll
            for (int nf = 0; nf < 4; nf++) {
#pragma unroll
                for (int h = 0; h < 2; h++) {
                    float v = colp[nf][h];
                    v += __shfl_xor_sync(0xffffffffu, v, 4);
                    v += __shfl_xor_sync(0xffffffffu, v, 8);
                    v += __shfl_xor_sync(0xffffffffu, v, 16);
                    if (lane < 4)
                        colarr[wm * 128 + wn * 32 + nf * 8 + lane * 2 + h] = v;
                }
            }
            __syncthreads();
            if (tid < 128) {
                float ctot = colarr[tid] + colarr[128 + tid];
                ps[(size_t)by * MB + bx * 128 + tid] = ctot;
            }
        }
    }

    // final row-sum reduction for the whole segment
#pragma unroll
    for (int f = 0; f < 4; f++) {
#pragma unroll
        for (int h = 0; h < 2; h++) {
            float v = rs[f][h];
            v += __shfl_xor_sync(0xffffffffu, v, 1);
            v += __shfl_xor_sync(0xffffffffu, v, 2);
            if ((lane & 3) == 0)
                lsum4[wn * 128 + wm * 64 + f * 16 + h * 8 + rsub] = v;
        }
    }
    __syncthreads();
    if (tid < 128) {
        float rtot = lsum4[tid] + lsum4[128 + tid] + lsum4[256 + tid] + lsum4[384 + tid];
        ps[(size_t)bx0 * MB + by * 128 + tid] = rtot;
        for (int c = bx0 + 1; c <= bx1; c++)
            ps[(size_t)c * MB + by * 128 + tid] = 0.f;
    }
}

// ---------------------------------------------------------------------------
__global__ void sumps_k(const float* __restrict__ ps, float* __restrict__ lse)
{
    const int row = blockIdx.x * 256 + threadIdx.x;
    float tot = 0.f;
#pragma unroll 8
    for (int c = 0; c < 128; c++) tot += ps[(size_t)c * MB + row];
    lse[row] = logf(tot) + INV_T;
}

__global__ void pos_k(const float* __restrict__ Z, float* __restrict__ pos)
{
    const int row = blockIdx.x;
    const int t = threadIdx.x;
    const int prow = (row + MB / 2) & (MB - 1);
    float s = Z[(size_t)row * FF + t] * Z[(size_t)prow * FF + t];
#pragma unroll
    for (int o = 16; o; o >>= 1) s += __shfl_xor_sync(0xffffffffu, s, o);
    __shared__ float ws[4];
    if ((t & 31) == 0) ws[t >> 5] = s;
    __syncthreads();
    if (t == 0) pos[row] = (ws[0] + ws[1] + ws[2] + ws[3]) * INV_T;
}

__global__ void loss_k(const float* __restrict__ lse, const float* __restrict__ pos,
                       float* __restrict__ out)
{
    __shared__ float sm[256];
    const int t = threadIdx.x;
    float s = 0.f;
    for (int i = t; i < MB; i += 256) s += lse[i] - pos[i];
    sm[t] = s;
    __syncthreads();
    for (int o = 128; o; o >>= 1) {
        if (t < o) sm[t] += sm[t + o];
        __syncthreads();
    }
    if (t == 0) out[0] = sm[0] * (1.0f / MB);
}

// ---------------------------------------------------------------------------
extern "C" void kernel_launch(void* const* d_in, const int* in_sizes, int n_in,
                              void* d_out, int out_size)
{
    const float* features = (const float*)d_in[0];
    const float* w1 = (const float*)d_in[1];
    const float* b1 = (const float*)d_in[2];
    const float* w2 = (const float*)d_in[3];
    const float* b2 = (const float*)d_in[4];
    float* out = (float*)d_out;

    __half *fhi, *w1hi, *w2hi, *hhi, *zhi;
    float *z, *p4b, *psb, *lseb, *posb;
    cudaGetSymbolAddress((void**)&fhi,  g_fhi);
    cudaGetSymbolAddress((void**)&w1hi, g_w1hi);
    cudaGetSymbolAddress((void**)&w2hi, g_w2hi);
    cudaGetSymbolAddress((void**)&hhi,  g_hhi);
    cudaGetSymbolAddress((void**)&zhi,  g_zhi);
    cudaGetSymbolAddress((void**)&z,    g_z);
    cudaGetSymbolAddress((void**)&p4b,  g_p4);
    cudaGetSymbolAddress((void**)&psb,  g_ps);
    cudaGetSymbolAddress((void**)&lseb, g_lse);
    cudaGetSymbolAddress((void**)&posb, g_pos);

    const int SM_G1 = 147456 + 512;          // 3 stages x 48KB + bias
    const int SM_G2 = 98304;                 // 4 stages x 24KB
    const int SM_L  = 98304 + 1024 + 2048;   // A + 2xB + colarr + lsum
    cudaFuncSetAttribute(hgemm1_k,   cudaFuncAttributeMaxDynamicSharedMemorySize, SM_G1);
    cudaFuncSetAttribute(hgemm2_k,   cudaFuncAttributeMaxDynamicSharedMemorySize, SM_G2);
    cudaFuncSetAttribute(lse_strip_k, cudaFuncAttributeMaxDynamicSharedMemorySize, SM_L);

    // prep
    cvt_k<<<2048, 256>>>(features, fhi, (size_t)MB * DD);
    tprep_k<<<dim3(64 + FF / 32, KK / 32), dim3(32, 8)>>>(w1, w2, w1hi, w2hi);

    // 1) h = relu(features @ w1 + b1)
    hgemm1_k<<<dim3(HH / 128, MB / 256), 512, SM_G1>>>(fhi, w1hi, b1, HH, hhi);

    // 2) p partials (split-K=4), then combine + L2-normalize
    hgemm2_k<<<dim3(4, MB / 256), 512, SM_G2>>>(hhi, w2hi, p4b);
    float* outz = (out_size >= 1 + MB * FF) ? (out + 1) : nullptr;
    combine_k<<<MB, 128>>>(p4b, b2, z, zhi, outz);

    // 3) pos
    pos_k<<<MB, 128>>>(z, posb);

    // 4) strip-streamed triangular masked exp-sum tiles
    lse_strip_k<<<dim3((MB / 128 + SEG - 1) / SEG, MB / 128), 256, SM_L>>>(zhi, psb);

    // 5) combine partials -> lse, 6) loss
    sumps_k<<<MB / 256, 256>>>(psb, lseb);
    loss_k<<<1, 256>>>(lseb, posb, out);
}